// round 1
// baseline (speedup 1.0000x reference)
#include <cuda_runtime.h>
#include <cstdint>

// ---------------------------------------------------------------------------
// Problem constants
//   B=8, TGT=256, SRC=512, D=1024, H=16, dh=64, TEMP=0.2, scale=dh^-0.5=1/8
// Inputs (metadata order): seqs(8,256,1024) keys(8,512,1024) q_w(1024,1024)
//   q_b(1024) k_w(1024,1024) k_b(1024) energy_bias(1)
// Output: p_choose (8,16,256,512) then alpha (8,16,256,512), fp32.
// ---------------------------------------------------------------------------

#define D_DIM   1024
#define TGT     256
#define SRC     512
#define NB      8
#define NH      16
#define DH      64
#define BH      (NB*NH)           // 128
#define P_ELEMS ((size_t)BH*TGT*SRC)  // 16,777,216

// scratch for projected activations (device globals: no allocation allowed)
__device__ float g_q[NB*TGT*D_DIM];   // (2048,1024)
__device__ float g_k[NB*SRC*D_DIM];   // (4096,1024)

// packed f32x2 FMA (sm_100+): 2x fp32 throughput vs scalar FFMA on B300
__device__ __forceinline__ void fma2(float2& c, const float2 a, const float2 b) {
    asm volatile("fma.rn.f32x2 %0, %1, %2, %0;"
        : "+l"(reinterpret_cast<unsigned long long&>(c))
        : "l"(reinterpret_cast<const unsigned long long&>(const_cast<float2&>(a))),
          "l"(reinterpret_cast<const unsigned long long&>(const_cast<float2&>(b))));
}

// ---------------------------------------------------------------------------
// Projection GEMM + bias + ReLU:  C[m,n] = relu(sum_k A[m,k]*W[n,k] + bias[n])
// A: (M,1024) row-major, W: (1024,1024) row-major (both K-major -> symmetric)
// Tile 128x128, BK=16, 256 threads, 8x8 per thread, f32x2 inner product.
// ---------------------------------------------------------------------------
__global__ __launch_bounds__(256)
void proj_kernel(const float* __restrict__ A, const float* __restrict__ W,
                 const float* __restrict__ bias, float* __restrict__ C, int M)
{
    __shared__ float As[16][129];
    __shared__ float Ws[16][130];

    const int bn = blockIdx.x * 128;
    const int bm = blockIdx.y * 128;
    const int tid = threadIdx.x;
    const int lr  = tid >> 2;          // 0..63
    const int lc  = (tid & 3) * 4;     // 0,4,8,12
    const int tm  = (tid >> 4) * 8;    // 0..120
    const int tn  = (tid & 15) * 8;    // 0..120

    float2 acc[8][4];
#pragma unroll
    for (int i = 0; i < 8; i++)
#pragma unroll
        for (int j = 0; j < 4; j++) acc[i][j] = make_float2(0.f, 0.f);

    const float* Aptr = A + (size_t)(bm + lr) * D_DIM + lc;
    const float* Wptr = W + (size_t)(bn + lr) * D_DIM + lc;

    for (int k0 = 0; k0 < D_DIM; k0 += 16) {
        float4 a0 = *(const float4*)(Aptr + k0);
        float4 a1 = *(const float4*)(Aptr + (size_t)64 * D_DIM + k0);
        float4 w0 = *(const float4*)(Wptr + k0);
        float4 w1 = *(const float4*)(Wptr + (size_t)64 * D_DIM + k0);
        __syncthreads();
        As[lc+0][lr] = a0.x; As[lc+1][lr] = a0.y; As[lc+2][lr] = a0.z; As[lc+3][lr] = a0.w;
        As[lc+0][lr+64] = a1.x; As[lc+1][lr+64] = a1.y; As[lc+2][lr+64] = a1.z; As[lc+3][lr+64] = a1.w;
        Ws[lc+0][lr] = w0.x; Ws[lc+1][lr] = w0.y; Ws[lc+2][lr] = w0.z; Ws[lc+3][lr] = w0.w;
        Ws[lc+0][lr+64] = w1.x; Ws[lc+1][lr+64] = w1.y; Ws[lc+2][lr+64] = w1.z; Ws[lc+3][lr+64] = w1.w;
        __syncthreads();
#pragma unroll
        for (int kk = 0; kk < 16; kk++) {
            float ra[8];
            float2 rb[4];
#pragma unroll
            for (int i = 0; i < 8; i++) ra[i] = As[kk][tm + i];
#pragma unroll
            for (int j = 0; j < 4; j++) rb[j] = *(const float2*)&Ws[kk][tn + 2*j];
#pragma unroll
            for (int i = 0; i < 8; i++) {
                float2 a2 = make_float2(ra[i], ra[i]);
#pragma unroll
                for (int j = 0; j < 4; j++) fma2(acc[i][j], a2, rb[j]);
            }
        }
    }

    float2 b2[4];
#pragma unroll
    for (int j = 0; j < 4; j++) b2[j] = *(const float2*)&bias[bn + tn + 2*j];

#pragma unroll
    for (int i = 0; i < 8; i++) {
        float4 o0, o1;
        o0.x = fmaxf(acc[i][0].x + b2[0].x, 0.f);
        o0.y = fmaxf(acc[i][0].y + b2[0].y, 0.f);
        o0.z = fmaxf(acc[i][1].x + b2[1].x, 0.f);
        o0.w = fmaxf(acc[i][1].y + b2[1].y, 0.f);
        o1.x = fmaxf(acc[i][2].x + b2[2].x, 0.f);
        o1.y = fmaxf(acc[i][2].y + b2[2].y, 0.f);
        o1.z = fmaxf(acc[i][3].x + b2[3].x, 0.f);
        o1.w = fmaxf(acc[i][3].y + b2[3].y, 0.f);
        float* cp = C + (size_t)(bm + tm + i) * D_DIM + bn + tn;
        *(float4*)(cp)     = o0;
        *(float4*)(cp + 4) = o1;
    }
}

// ---------------------------------------------------------------------------
// Energy + sigmoid:  per (b,h):  E = q_bh (256x64) @ k_bh^T (512x64)^T
//   p = sigmoid((E/8 + eb) * 5)
// Tile 64(M) x 128(N), BK=32, 256 threads, 4x8 per thread.
// ---------------------------------------------------------------------------
__global__ __launch_bounds__(256)
void energy_kernel(const float* __restrict__ Q, const float* __restrict__ Kp,
                   const float* __restrict__ ebias, float* __restrict__ P)
{
    __shared__ float Qs[32][65];
    __shared__ float Ks[32][130];

    const int bh = blockIdx.z;
    const int bb = bh >> 4;
    const int hh = bh & 15;
    const int m0 = blockIdx.y * 64;
    const int n0 = blockIdx.x * 128;
    const int tid = threadIdx.x;

    const float* Qbase = Q + (size_t)bb * TGT * D_DIM + hh * DH;
    const float* Kbase = Kp + (size_t)bb * SRC * D_DIM + hh * DH;

    const int qr = tid >> 3;         // 0..31
    const int qc = (tid & 7) * 4;    // 0..28
    const int tmr = (tid >> 4) * 4;  // 0..60
    const int tnc = (tid & 15) * 8;  // 0..120

    float2 acc[4][4];
#pragma unroll
    for (int i = 0; i < 4; i++)
#pragma unroll
        for (int j = 0; j < 4; j++) acc[i][j] = make_float2(0.f, 0.f);

    for (int k0 = 0; k0 < DH; k0 += 32) {
        float4 v0 = *(const float4*)(Qbase + (size_t)(m0 + qr) * D_DIM + k0 + qc);
        float4 v1 = *(const float4*)(Qbase + (size_t)(m0 + qr + 32) * D_DIM + k0 + qc);
        float4 w0 = *(const float4*)(Kbase + (size_t)(n0 + qr) * D_DIM + k0 + qc);
        float4 w1 = *(const float4*)(Kbase + (size_t)(n0 + qr + 32) * D_DIM + k0 + qc);
        float4 w2 = *(const float4*)(Kbase + (size_t)(n0 + qr + 64) * D_DIM + k0 + qc);
        float4 w3 = *(const float4*)(Kbase + (size_t)(n0 + qr + 96) * D_DIM + k0 + qc);
        __syncthreads();
        Qs[qc+0][qr] = v0.x; Qs[qc+1][qr] = v0.y; Qs[qc+2][qr] = v0.z; Qs[qc+3][qr] = v0.w;
        Qs[qc+0][qr+32] = v1.x; Qs[qc+1][qr+32] = v1.y; Qs[qc+2][qr+32] = v1.z; Qs[qc+3][qr+32] = v1.w;
        Ks[qc+0][qr] = w0.x; Ks[qc+1][qr] = w0.y; Ks[qc+2][qr] = w0.z; Ks[qc+3][qr] = w0.w;
        Ks[qc+0][qr+32] = w1.x; Ks[qc+1][qr+32] = w1.y; Ks[qc+2][qr+32] = w1.z; Ks[qc+3][qr+32] = w1.w;
        Ks[qc+0][qr+64] = w2.x; Ks[qc+1][qr+64] = w2.y; Ks[qc+2][qr+64] = w2.z; Ks[qc+3][qr+64] = w2.w;
        Ks[qc+0][qr+96] = w3.x; Ks[qc+1][qr+96] = w3.y; Ks[qc+2][qr+96] = w3.z; Ks[qc+3][qr+96] = w3.w;
        __syncthreads();
#pragma unroll
        for (int kk = 0; kk < 32; kk++) {
            float ra[4];
            float2 rb[4];
#pragma unroll
            for (int i = 0; i < 4; i++) ra[i] = Qs[kk][tmr + i];
#pragma unroll
            for (int j = 0; j < 4; j++) rb[j] = *(const float2*)&Ks[kk][tnc + 2*j];
#pragma unroll
            for (int i = 0; i < 4; i++) {
                float2 a2 = make_float2(ra[i], ra[i]);
#pragma unroll
                for (int j = 0; j < 4; j++) fma2(acc[i][j], a2, rb[j]);
            }
        }
    }

    const float eb5 = ebias[0] * 5.0f;      // (E*0.125 + eb)*5 = E*0.625 + eb*5

#pragma unroll
    for (int i = 0; i < 4; i++) {
        float e[8];
        e[0]=acc[i][0].x; e[1]=acc[i][0].y; e[2]=acc[i][1].x; e[3]=acc[i][1].y;
        e[4]=acc[i][2].x; e[5]=acc[i][2].y; e[6]=acc[i][3].x; e[7]=acc[i][3].y;
        float4 o0, o1;
        float* po = (float*)&o0;
#pragma unroll
        for (int j = 0; j < 8; j++) {
            float z = fmaf(e[j], 0.625f, eb5);
            float p = 1.0f / (1.0f + __expf(-z));
            if (j < 4) ((float*)&o0)[j] = p; else ((float*)&o1)[j-4] = p;
        }
        (void)po;
        float* dst = P + ((size_t)bh * TGT + (m0 + tmr + i)) * SRC + n0 + tnc;
        *(float4*)(dst)     = o0;
        *(float4*)(dst + 4) = o1;
    }
}

// ---------------------------------------------------------------------------
// Monotonic alignment:
//   q_i[n] = alpha_{i-1}[n] + q_i[n-1]*(1-p_i[n-1]),  alpha_i[n] = p_i[n]*q_i[n]
// One warp per (b,h) row. Each lane owns 16 contiguous src columns.
// Per target step: serial chunk composition -> 5-level shfl scan of the
// linear-recurrence operator (a,b) -> replay. Next p row prefetched.
// ---------------------------------------------------------------------------
__global__ __launch_bounds__(128)
void alpha_kernel(const float* __restrict__ p, float* __restrict__ alpha)
{
    const int warp = threadIdx.x >> 5;
    const int lane = threadIdx.x & 31;
    const int bh   = blockIdx.x * 4 + warp;

    const float* prow = p     + (size_t)bh * TGT * SRC + lane * 16;
    float*       arow = alpha + (size_t)bh * TGT * SRC + lane * 16;

    float Bv[16];
#pragma unroll
    for (int j = 0; j < 16; j++) Bv[j] = 0.f;
    if (lane == 0) Bv[0] = 1.f;      // alpha_{-1} = delta_0

    float4 nb0 = *(const float4*)(prow + 0);
    float4 nb1 = *(const float4*)(prow + 4);
    float4 nb2 = *(const float4*)(prow + 8);
    float4 nb3 = *(const float4*)(prow + 12);

    for (int i = 0; i < TGT; i++) {
        float pc[16];
        pc[0]=nb0.x; pc[1]=nb0.y; pc[2]=nb0.z; pc[3]=nb0.w;
        pc[4]=nb1.x; pc[5]=nb1.y; pc[6]=nb1.z; pc[7]=nb1.w;
        pc[8]=nb2.x; pc[9]=nb2.y; pc[10]=nb2.z; pc[11]=nb2.w;
        pc[12]=nb3.x; pc[13]=nb3.y; pc[14]=nb3.z; pc[15]=nb3.w;

        if (i + 1 < TGT) {              // prefetch next row (hides DRAM/L2 latency)
            const float* np = prow + (size_t)(i + 1) * SRC;
            nb0 = *(const float4*)(np + 0);
            nb1 = *(const float4*)(np + 4);
            nb2 = *(const float4*)(np + 8);
            nb3 = *(const float4*)(np + 12);
        }

        // A[0] of this chunk needs p of the previous lane's last element
        float prevlast = __shfl_up_sync(0xffffffffu, pc[15], 1);
        float a0 = (lane == 0) ? 0.f : (1.f - prevlast);

        // local composition of 16 recurrence steps: (a,b) s.t. q_out = q_in*a + b
        float a = a0;
        float b = Bv[0];
#pragma unroll
        for (int j = 1; j < 16; j++) {
            float Aj = 1.f - pc[j-1];
            a *= Aj;
            b = fmaf(b, Aj, Bv[j]);
        }

        // inclusive warp scan under composition (a2,b2) then (a,b):
        //   b = b2*a + b ; a = a2*a
#pragma unroll
        for (int d = 1; d < 32; d <<= 1) {
            float a2 = __shfl_up_sync(0xffffffffu, a, d);
            float b2 = __shfl_up_sync(0xffffffffu, b, d);
            if (lane >= d) { b = fmaf(b2, a, b); a = a2 * a; }
        }

        // incoming q for this chunk = inclusive value of lane-1 (q starts at 0)
        float qin = __shfl_up_sync(0xffffffffu, b, 1);
        if (lane == 0) qin = 0.f;

        // replay: q_j = q_{j-1}*A[j] + B[j];  alpha_i = p * q
        float q = fmaf(qin, a0, Bv[0]);
        Bv[0] = pc[0] * q;
#pragma unroll
        for (int j = 1; j < 16; j++) {
            q = fmaf(q, 1.f - pc[j-1], Bv[j]);
            Bv[j] = pc[j] * q;
        }

        float* dst = arow + (size_t)i * SRC;
        *(float4*)(dst + 0)  = make_float4(Bv[0],  Bv[1],  Bv[2],  Bv[3]);
        *(float4*)(dst + 4)  = make_float4(Bv[4],  Bv[5],  Bv[6],  Bv[7]);
        *(float4*)(dst + 8)  = make_float4(Bv[8],  Bv[9],  Bv[10], Bv[11]);
        *(float4*)(dst + 12) = make_float4(Bv[12], Bv[13], Bv[14], Bv[15]);
    }
}

// ---------------------------------------------------------------------------
extern "C" void kernel_launch(void* const* d_in, const int* in_sizes, int n_in,
                              void* d_out, int out_size)
{
    const float* seqs  = (const float*)d_in[0];
    const float* keys  = (const float*)d_in[1];
    const float* q_w   = (const float*)d_in[2];
    const float* q_b   = (const float*)d_in[3];
    const float* k_w   = (const float*)d_in[4];
    const float* k_b   = (const float*)d_in[5];
    const float* ebias = (const float*)d_in[6];

    float* p_out = (float*)d_out;            // (8,16,256,512)
    float* a_out = p_out + P_ELEMS;          // alpha

    float* gq; cudaGetSymbolAddress((void**)&gq, g_q);
    float* gk; cudaGetSymbolAddress((void**)&gk, g_k);

    dim3 t256(256);
    proj_kernel<<<dim3(8, 16), t256>>>(seqs, q_w, q_b, gq, NB*TGT);   // 2048x1024
    proj_kernel<<<dim3(8, 32), t256>>>(keys, k_w, k_b, gk, NB*SRC);   // 4096x1024
    energy_kernel<<<dim3(4, 4, BH), t256>>>(gq, gk, ebias, p_out);
    alpha_kernel<<<32, 128>>>(p_out, a_out);
}

// round 2
// speedup vs baseline: 1.0274x; 1.0274x over previous
#include <cuda_runtime.h>
#include <cstdint>

// ---------------------------------------------------------------------------
// B=8, TGT=256, SRC=512, D=1024, H=16, dh=64, TEMP=0.2
// Output: p_choose (8,16,256,512) then alpha (8,16,256,512), fp32.
// ---------------------------------------------------------------------------

#define D_DIM   1024
#define TGT     256
#define SRC     512
#define NB      8
#define NH      16
#define DH      64
#define BH      (NB*NH)
#define P_ELEMS ((size_t)BH*TGT*SRC)

__device__ float g_q[NB*TGT*D_DIM];
__device__ float g_k[NB*SRC*D_DIM];

__device__ __forceinline__ void fma2(float2& c, const float2 a, const float2 b) {
    asm volatile("fma.rn.f32x2 %0, %1, %2, %0;"
        : "+l"(reinterpret_cast<unsigned long long&>(c))
        : "l"(reinterpret_cast<const unsigned long long&>(const_cast<float2&>(a))),
          "l"(reinterpret_cast<const unsigned long long&>(const_cast<float2&>(b))));
}

// ---------------------------------------------------------------------------
// Merged projection GEMM + bias + ReLU, double-buffered smem.
// blockIdx.y < 16 -> q path (seqs @ q_w^T), else k path (keys @ k_w^T).
// Tile 128x128, BK=16, 256 threads, 8x8/thread, f32x2.
// ---------------------------------------------------------------------------
__global__ __launch_bounds__(256)
void proj_kernel(const float* __restrict__ seqs, const float* __restrict__ keys,
                 const float* __restrict__ q_w, const float* __restrict__ q_b,
                 const float* __restrict__ k_w, const float* __restrict__ k_b,
                 float* __restrict__ gq, float* __restrict__ gk)
{
    __shared__ float As[2][16][132];
    __shared__ float Ws[2][16][132];

    const int by = blockIdx.y;
    const bool isq = by < 16;
    const float* A    = isq ? seqs : keys;
    const float* W    = isq ? q_w  : k_w;
    const float* bias = isq ? q_b  : k_b;
    float*       C    = isq ? gq   : gk;
    const int bm = (isq ? by : by - 16) * 128;
    const int bn = blockIdx.x * 128;

    const int tid = threadIdx.x;
    const int lr  = tid >> 2;          // 0..63
    const int lc  = (tid & 3) * 4;     // 0,4,8,12
    const int tm  = (tid >> 4) * 8;
    const int tn  = (tid & 15) * 8;

    float2 acc[8][4];
#pragma unroll
    for (int i = 0; i < 8; i++)
#pragma unroll
        for (int j = 0; j < 4; j++) acc[i][j] = make_float2(0.f, 0.f);

    const float* Aptr = A + (size_t)(bm + lr) * D_DIM + lc;
    const float* Wptr = W + (size_t)(bn + lr) * D_DIM + lc;

    // ---- prologue: load k0=0, store to buffer 0 ----
    {
        float4 a0 = *(const float4*)(Aptr);
        float4 a1 = *(const float4*)(Aptr + (size_t)64 * D_DIM);
        float4 w0 = *(const float4*)(Wptr);
        float4 w1 = *(const float4*)(Wptr + (size_t)64 * D_DIM);
#pragma unroll
        for (int i = 0; i < 4; i++) {
            As[0][lc+i][lr]    = ((const float*)&a0)[i];
            As[0][lc+i][lr+64] = ((const float*)&a1)[i];
            Ws[0][lc+i][lr]    = ((const float*)&w0)[i];
            Ws[0][lc+i][lr+64] = ((const float*)&w1)[i];
        }
    }
    __syncthreads();

    int cur = 0;
    for (int k0 = 16; k0 < D_DIM; k0 += 16) {
        // issue next-tile loads early (hidden under compute below)
        float4 a0 = *(const float4*)(Aptr + k0);
        float4 a1 = *(const float4*)(Aptr + (size_t)64 * D_DIM + k0);
        float4 w0 = *(const float4*)(Wptr + k0);
        float4 w1 = *(const float4*)(Wptr + (size_t)64 * D_DIM + k0);

        const float (*Ac)[132] = As[cur];
        const float (*Wc)[132] = Ws[cur];
#pragma unroll
        for (int kk = 0; kk < 16; kk++) {
            float4 ra0 = *(const float4*)&Ac[kk][tm];
            float4 ra1 = *(const float4*)&Ac[kk][tm+4];
            float4 rb0 = *(const float4*)&Wc[kk][tn];
            float4 rb1 = *(const float4*)&Wc[kk][tn+4];
            float2 rb[4];
            rb[0] = make_float2(rb0.x, rb0.y); rb[1] = make_float2(rb0.z, rb0.w);
            rb[2] = make_float2(rb1.x, rb1.y); rb[3] = make_float2(rb1.z, rb1.w);
            float ra[8] = {ra0.x, ra0.y, ra0.z, ra0.w, ra1.x, ra1.y, ra1.z, ra1.w};
#pragma unroll
            for (int i = 0; i < 8; i++) {
                float2 a2 = make_float2(ra[i], ra[i]);
#pragma unroll
                for (int j = 0; j < 4; j++) fma2(acc[i][j], a2, rb[j]);
            }
        }

        const int nxt = cur ^ 1;
#pragma unroll
        for (int i = 0; i < 4; i++) {
            As[nxt][lc+i][lr]    = ((const float*)&a0)[i];
            As[nxt][lc+i][lr+64] = ((const float*)&a1)[i];
            Ws[nxt][lc+i][lr]    = ((const float*)&w0)[i];
            Ws[nxt][lc+i][lr+64] = ((const float*)&w1)[i];
        }
        __syncthreads();
        cur = nxt;
    }

    // last tile compute
    {
        const float (*Ac)[132] = As[cur];
        const float (*Wc)[132] = Ws[cur];
#pragma unroll
        for (int kk = 0; kk < 16; kk++) {
            float4 ra0 = *(const float4*)&Ac[kk][tm];
            float4 ra1 = *(const float4*)&Ac[kk][tm+4];
            float4 rb0 = *(const float4*)&Wc[kk][tn];
            float4 rb1 = *(const float4*)&Wc[kk][tn+4];
            float2 rb[4];
            rb[0] = make_float2(rb0.x, rb0.y); rb[1] = make_float2(rb0.z, rb0.w);
            rb[2] = make_float2(rb1.x, rb1.y); rb[3] = make_float2(rb1.z, rb1.w);
            float ra[8] = {ra0.x, ra0.y, ra0.z, ra0.w, ra1.x, ra1.y, ra1.z, ra1.w};
#pragma unroll
            for (int i = 0; i < 8; i++) {
                float2 a2 = make_float2(ra[i], ra[i]);
#pragma unroll
                for (int j = 0; j < 4; j++) fma2(acc[i][j], a2, rb[j]);
            }
        }
    }

    float2 b2[4];
#pragma unroll
    for (int j = 0; j < 4; j++) b2[j] = *(const float2*)&bias[bn + tn + 2*j];

#pragma unroll
    for (int i = 0; i < 8; i++) {
        float4 o0, o1;
        o0.x = fmaxf(acc[i][0].x + b2[0].x, 0.f);
        o0.y = fmaxf(acc[i][0].y + b2[0].y, 0.f);
        o0.z = fmaxf(acc[i][1].x + b2[1].x, 0.f);
        o0.w = fmaxf(acc[i][1].y + b2[1].y, 0.f);
        o1.x = fmaxf(acc[i][2].x + b2[2].x, 0.f);
        o1.y = fmaxf(acc[i][2].y + b2[2].y, 0.f);
        o1.z = fmaxf(acc[i][3].x + b2[3].x, 0.f);
        o1.w = fmaxf(acc[i][3].y + b2[3].y, 0.f);
        float* cp = C + (size_t)(bm + tm + i) * D_DIM + bn + tn;
        *(float4*)(cp)     = o0;
        *(float4*)(cp + 4) = o1;
    }
}

// ---------------------------------------------------------------------------
// Energy + sigmoid (unchanged from passing R1 version).
// ---------------------------------------------------------------------------
__global__ __launch_bounds__(256)
void energy_kernel(const float* __restrict__ Q, const float* __restrict__ Kp,
                   const float* __restrict__ ebias, float* __restrict__ P)
{
    __shared__ float Qs[32][65];
    __shared__ float Ks[32][130];

    const int bh = blockIdx.z;
    const int bb = bh >> 4;
    const int hh = bh & 15;
    const int m0 = blockIdx.y * 64;
    const int n0 = blockIdx.x * 128;
    const int tid = threadIdx.x;

    const float* Qbase = Q + (size_t)bb * TGT * D_DIM + hh * DH;
    const float* Kbase = Kp + (size_t)bb * SRC * D_DIM + hh * DH;

    const int qr = tid >> 3;
    const int qc = (tid & 7) * 4;
    const int tmr = (tid >> 4) * 4;
    const int tnc = (tid & 15) * 8;

    float2 acc[4][4];
#pragma unroll
    for (int i = 0; i < 4; i++)
#pragma unroll
        for (int j = 0; j < 4; j++) acc[i][j] = make_float2(0.f, 0.f);

    for (int k0 = 0; k0 < DH; k0 += 32) {
        float4 v0 = *(const float4*)(Qbase + (size_t)(m0 + qr) * D_DIM + k0 + qc);
        float4 v1 = *(const float4*)(Qbase + (size_t)(m0 + qr + 32) * D_DIM + k0 + qc);
        float4 w0 = *(const float4*)(Kbase + (size_t)(n0 + qr) * D_DIM + k0 + qc);
        float4 w1 = *(const float4*)(Kbase + (size_t)(n0 + qr + 32) * D_DIM + k0 + qc);
        float4 w2 = *(const float4*)(Kbase + (size_t)(n0 + qr + 64) * D_DIM + k0 + qc);
        float4 w3 = *(const float4*)(Kbase + (size_t)(n0 + qr + 96) * D_DIM + k0 + qc);
        __syncthreads();
        Qs[qc+0][qr] = v0.x; Qs[qc+1][qr] = v0.y; Qs[qc+2][qr] = v0.z; Qs[qc+3][qr] = v0.w;
        Qs[qc+0][qr+32] = v1.x; Qs[qc+1][qr+32] = v1.y; Qs[qc+2][qr+32] = v1.z; Qs[qc+3][qr+32] = v1.w;
        Ks[qc+0][qr] = w0.x; Ks[qc+1][qr] = w0.y; Ks[qc+2][qr] = w0.z; Ks[qc+3][qr] = w0.w;
        Ks[qc+0][qr+32] = w1.x; Ks[qc+1][qr+32] = w1.y; Ks[qc+2][qr+32] = w1.z; Ks[qc+3][qr+32] = w1.w;
        Ks[qc+0][qr+64] = w2.x; Ks[qc+1][qr+64] = w2.y; Ks[qc+2][qr+64] = w2.z; Ks[qc+3][qr+64] = w2.w;
        Ks[qc+0][qr+96] = w3.x; Ks[qc+1][qr+96] = w3.y; Ks[qc+2][qr+96] = w3.z; Ks[qc+3][qr+96] = w3.w;
        __syncthreads();
#pragma unroll
        for (int kk = 0; kk < 32; kk++) {
            float ra[4];
            float2 rb[4];
#pragma unroll
            for (int i = 0; i < 4; i++) ra[i] = Qs[kk][tmr + i];
#pragma unroll
            for (int j = 0; j < 4; j++) rb[j] = *(const float2*)&Ks[kk][tnc + 2*j];
#pragma unroll
            for (int i = 0; i < 4; i++) {
                float2 a2 = make_float2(ra[i], ra[i]);
#pragma unroll
                for (int j = 0; j < 4; j++) fma2(acc[i][j], a2, rb[j]);
            }
        }
    }

    const float eb5 = ebias[0] * 5.0f;

#pragma unroll
    for (int i = 0; i < 4; i++) {
        float e[8];
        e[0]=acc[i][0].x; e[1]=acc[i][0].y; e[2]=acc[i][1].x; e[3]=acc[i][1].y;
        e[4]=acc[i][2].x; e[5]=acc[i][2].y; e[6]=acc[i][3].x; e[7]=acc[i][3].y;
        float4 o0, o1;
#pragma unroll
        for (int j = 0; j < 8; j++) {
            float z = fmaf(e[j], 0.625f, eb5);
            float pv = 1.0f / (1.0f + __expf(-z));
            if (j < 4) ((float*)&o0)[j] = pv; else ((float*)&o1)[j-4] = pv;
        }
        float* dst = P + ((size_t)bh * TGT + (m0 + tmr + i)) * SRC + n0 + tnc;
        *(float4*)(dst)     = o0;
        *(float4*)(dst + 4) = o1;
    }
}

// ---------------------------------------------------------------------------
// Monotonic alignment v2.
//   q[n] = q[n-1]*A[n] + B[n],  A[n]=1-p_i[n-1] (A[0]=0), B[n]=alpha_{i-1}[n]
//   alpha_i[n] = p_i[n]*q[n]
// One warp per (b,h) row, lane owns 16 contiguous cols. Per step:
//   - Pb serial chain (depends on prev alpha): 15 fma, ~60cy
//   - 5-level warp scan with PRECOMPUTED multipliers m_d (p-only, made last iter)
//   - qin shfl, then 16 INDEPENDENT replay fmas via precomputed prefixes Pa
// Prefetch depth 2 with streaming loads/stores.
// ---------------------------------------------------------------------------
__global__ __launch_bounds__(32)
void alpha_kernel(const float* __restrict__ p, float* __restrict__ alpha)
{
    const int lane = threadIdx.x;
    const int bh   = blockIdx.x;

    const float4* pr = (const float4*)(p     + (size_t)bh * TGT * SRC + lane * 16);
    float4*       ar = (float4*)      (alpha + (size_t)bh * TGT * SRC + lane * 16);
    // row stride = SRC/4 = 128 float4

    float4 buf[2][4];
#pragma unroll
    for (int j = 0; j < 4; j++) buf[0][j] = __ldcs(pr + j);
#pragma unroll
    for (int j = 0; j < 4; j++) buf[1][j] = __ldcs(pr + 128 + j);

    float Bv[16];
#pragma unroll
    for (int j = 0; j < 16; j++) Bv[j] = 0.f;
    if (lane == 0) Bv[0] = 1.f;   // alpha_{-1} = delta_0

    // ---- step-0 parameters from buf[0] ----
    float pc[16], Av[16], Pa[16];
    float m1, m2, m4, m8, m16;
    {
#pragma unroll
        for (int j = 0; j < 4; j++) {
            pc[4*j+0] = buf[0][j].x; pc[4*j+1] = buf[0][j].y;
            pc[4*j+2] = buf[0][j].z; pc[4*j+3] = buf[0][j].w;
        }
        float prevlast = __shfl_up_sync(0xffffffffu, pc[15], 1);
        Av[0] = (lane == 0) ? 0.f : (1.f - prevlast);
#pragma unroll
        for (int j = 1; j < 16; j++) Av[j] = 1.f - pc[j-1];
        Pa[0] = Av[0];
#pragma unroll
        for (int j = 1; j < 16; j++) Pa[j] = Pa[j-1] * Av[j];
        m1  = Pa[15];
        m2  = m1 * __shfl_up_sync(0xffffffffu, m1, 1);
        m4  = m2 * __shfl_up_sync(0xffffffffu, m2, 2);
        m8  = m4 * __shfl_up_sync(0xffffffffu, m4, 4);
        m16 = m8 * __shfl_up_sync(0xffffffffu, m8, 8);
    }

    for (int i = 0; i < TGT; i++) {
        // prefetch row i+2 into the buffer slot whose row i was already consumed
        if (i + 2 < TGT) {
            float4* bslot = buf[i & 1];
#pragma unroll
            for (int j = 0; j < 4; j++) bslot[j] = __ldcs(pr + (size_t)(i + 2) * 128 + j);
        }

        // ---- critical path: Pb chain -> scan -> qin -> replay ----
        float Pb[16];
        Pb[0] = Bv[0];
#pragma unroll
        for (int j = 1; j < 16; j++) Pb[j] = fmaf(Pb[j-1], Av[j], Bv[j]);

        float b = Pb[15];
        {
            float t;
            t = __shfl_up_sync(0xffffffffu, b, 1);  if (lane >= 1)  b = fmaf(t, m1,  b);
            t = __shfl_up_sync(0xffffffffu, b, 2);  if (lane >= 2)  b = fmaf(t, m2,  b);
            t = __shfl_up_sync(0xffffffffu, b, 4);  if (lane >= 4)  b = fmaf(t, m4,  b);
            t = __shfl_up_sync(0xffffffffu, b, 8);  if (lane >= 8)  b = fmaf(t, m8,  b);
            t = __shfl_up_sync(0xffffffffu, b, 16); if (lane >= 16) b = fmaf(t, m16, b);
        }
        float qin = __shfl_up_sync(0xffffffffu, b, 1);
        if (lane == 0) qin = 0.f;

        float al[16];
#pragma unroll
        for (int j = 0; j < 16; j++) {
            float q = fmaf(qin, Pa[j], Pb[j]);
            al[j] = pc[j] * q;
            Bv[j] = al[j];
        }

        // streaming stores (alpha is never re-read)
        __stcs(ar + (size_t)i * 128 + 0, make_float4(al[0],  al[1],  al[2],  al[3]));
        __stcs(ar + (size_t)i * 128 + 1, make_float4(al[4],  al[5],  al[6],  al[7]));
        __stcs(ar + (size_t)i * 128 + 2, make_float4(al[8],  al[9],  al[10], al[11]));
        __stcs(ar + (size_t)i * 128 + 3, make_float4(al[12], al[13], al[14], al[15]));

        // ---- prep step i+1 params (p-only; ptxas interleaves with stalls above) ----
        if (i + 1 < TGT) {
            const float4* bslot = buf[(i + 1) & 1];
#pragma unroll
            for (int j = 0; j < 4; j++) {
                pc[4*j+0] = bslot[j].x; pc[4*j+1] = bslot[j].y;
                pc[4*j+2] = bslot[j].z; pc[4*j+3] = bslot[j].w;
            }
            float prevlast = __shfl_up_sync(0xffffffffu, pc[15], 1);
            Av[0] = (lane == 0) ? 0.f : (1.f - prevlast);
#pragma unroll
            for (int j = 1; j < 16; j++) Av[j] = 1.f - pc[j-1];
            Pa[0] = Av[0];
#pragma unroll
            for (int j = 1; j < 16; j++) Pa[j] = Pa[j-1] * Av[j];
            m1  = Pa[15];
            m2  = m1 * __shfl_up_sync(0xffffffffu, m1, 1);
            m4  = m2 * __shfl_up_sync(0xffffffffu, m2, 2);
            m8  = m4 * __shfl_up_sync(0xffffffffu, m4, 4);
            m16 = m8 * __shfl_up_sync(0xffffffffu, m8, 8);
        }
    }
}

// ---------------------------------------------------------------------------
extern "C" void kernel_launch(void* const* d_in, const int* in_sizes, int n_in,
                              void* d_out, int out_size)
{
    const float* seqs  = (const float*)d_in[0];
    const float* keys  = (const float*)d_in[1];
    const float* q_w   = (const float*)d_in[2];
    const float* q_b   = (const float*)d_in[3];
    const float* k_w   = (const float*)d_in[4];
    const float* k_b   = (const float*)d_in[5];
    const float* ebias = (const float*)d_in[6];

    float* p_out = (float*)d_out;
    float* a_out = p_out + P_ELEMS;

    float* gq; cudaGetSymbolAddress((void**)&gq, g_q);
    float* gk; cudaGetSymbolAddress((void**)&gk, g_k);

    proj_kernel<<<dim3(8, 48), 256>>>(seqs, keys, q_w, q_b, k_w, k_b, gq, gk);
    energy_kernel<<<dim3(4, 4, BH), 256>>>(gq, gk, ebias, p_out);
    alpha_kernel<<<BH, 32>>>(p_out, a_out);
}

// round 4
// speedup vs baseline: 1.3853x; 1.3483x over previous
#include <cuda_runtime.h>
#include <cuda_bf16.h>
#include <cstdint>

// ---------------------------------------------------------------------------
// B=8, TGT=256, SRC=512, D=1024, H=16, dh=64, TEMP=0.2
// Output: p_choose (8,16,256,512) then alpha (8,16,256,512), fp32.
// ---------------------------------------------------------------------------

#define D_DIM   1024
#define TGT     256
#define SRC     512
#define NB      8
#define NH      16
#define DH      64
#define BH      (NB*NH)
#define P_ELEMS ((size_t)BH*TGT*SRC)

#define MQ (NB*TGT)     // 2048
#define MK (NB*SRC)     // 4096

// fp32 activations (projection outputs)
__device__ float g_q[MQ*D_DIM];
__device__ float g_k[MK*D_DIM];
// bf16 hi/lo decompositions
__device__ __nv_bfloat16 g_sh[MQ*D_DIM], g_sl[MQ*D_DIM];
__device__ __nv_bfloat16 g_kh[MK*D_DIM], g_kl[MK*D_DIM];
__device__ __nv_bfloat16 g_qwh[D_DIM*D_DIM], g_qwl[D_DIM*D_DIM];
__device__ __nv_bfloat16 g_kwh[D_DIM*D_DIM], g_kwl[D_DIM*D_DIM];

__device__ __forceinline__ void fma2(float2& c, const float2 a, const float2 b) {
    asm volatile("fma.rn.f32x2 %0, %1, %2, %0;"
        : "+l"(reinterpret_cast<unsigned long long&>(c))
        : "l"(reinterpret_cast<const unsigned long long&>(const_cast<float2&>(a))),
          "l"(reinterpret_cast<const unsigned long long&>(const_cast<float2&>(b))));
}

// warp-level bf16 mma (valid on compute_103 PTX; compiles to HMMA SASS)
__device__ __forceinline__ void mma16816(float4& d,
    uint32_t a0, uint32_t a1, uint32_t a2, uint32_t a3,
    uint32_t b0, uint32_t b1)
{
    asm volatile(
        "mma.sync.aligned.m16n8k16.row.col.f32.bf16.bf16.f32 "
        "{%0,%1,%2,%3}, {%4,%5,%6,%7}, {%8,%9}, {%0,%1,%2,%3};"
        : "+f"(d.x), "+f"(d.y), "+f"(d.z), "+f"(d.w)
        : "r"(a0), "r"(a1), "r"(a2), "r"(a3), "r"(b0), "r"(b1));
}

__device__ __forceinline__ void cp_async16(uint32_t smem_dst, const void* gsrc) {
    asm volatile("cp.async.ca.shared.global [%0], [%1], 16;" :: "r"(smem_dst), "l"(gsrc));
}
__device__ __forceinline__ void cp_async_commit() {
    asm volatile("cp.async.commit_group;" ::: "memory");
}
__device__ __forceinline__ void cp_async_wait0() {
    asm volatile("cp.async.wait_group 0;" ::: "memory");
}
__device__ __forceinline__ uint32_t smem_u32(const void* p) {
    uint32_t a;
    asm("{ .reg .u64 t; cvta.to.shared.u64 t, %1; cvt.u32.u64 %0, t; }" : "=r"(a) : "l"(p));
    return a;
}

// ---------------------------------------------------------------------------
// fp32 -> (hi, lo) bf16 decomposition. x ~= hi + lo (~16 mantissa bits).
// ---------------------------------------------------------------------------
__global__ __launch_bounds__(256)
void cvt_kernel(const float4* __restrict__ in, ushort4* __restrict__ hi,
                ushort4* __restrict__ lo, int n4)
{
    int i = blockIdx.x * 256 + threadIdx.x;
    if (i >= n4) return;
    float4 v = in[i];
    ushort4 h, l;
    {
        __nv_bfloat16 hb = __float2bfloat16(v.x);
        __nv_bfloat16 lb = __float2bfloat16(v.x - __bfloat162float(hb));
        h.x = *(unsigned short*)&hb; l.x = *(unsigned short*)&lb;
    }
    {
        __nv_bfloat16 hb = __float2bfloat16(v.y);
        __nv_bfloat16 lb = __float2bfloat16(v.y - __bfloat162float(hb));
        h.y = *(unsigned short*)&hb; l.y = *(unsigned short*)&lb;
    }
    {
        __nv_bfloat16 hb = __float2bfloat16(v.z);
        __nv_bfloat16 lb = __float2bfloat16(v.z - __bfloat162float(hb));
        h.z = *(unsigned short*)&hb; l.z = *(unsigned short*)&lb;
    }
    {
        __nv_bfloat16 hb = __float2bfloat16(v.w);
        __nv_bfloat16 lb = __float2bfloat16(v.w - __bfloat162float(hb));
        h.w = *(unsigned short*)&hb; l.w = *(unsigned short*)&lb;
    }
    hi[i] = h; lo[i] = l;
}

// ---------------------------------------------------------------------------
// mma.sync bf16-split projection GEMM + bias + ReLU.
// C[m,n] = relu( sum_k A[m,k]*W[n,k] + bias[n] ),  A~Ah+Al, W~Wh+Wl,
// C = Ah*Wh + Ah*Wl + Al*Wh in fp32 accumulators.
// CTA tile 128x128, 8 warps (4M x 2N), warp tile 32x64.
// K chunked by 32, cp.async double buffer.
// ---------------------------------------------------------------------------
#define CK      32                    // k per chunk
#define NCH     (D_DIM/CK)            // 32
#define STR     40                    // smem row stride (bf16 elems): conflict-free
#define TILE_E  (128*STR)             // 5120 elems
#define TILE_BYTES (TILE_E*2)         // 10240
#define BUF_BYTES  (4*TILE_BYTES)     // Ah, Al, Wh, Wl = 40960
#define PROJ_SMEM  (2*BUF_BYTES)      // 81920

__global__ __launch_bounds__(256)
void proj_mma(const float* __restrict__ q_b, const float* __restrict__ k_b)
{
    extern __shared__ char smem[];
    const int tid  = threadIdx.x;
    const int wid  = tid >> 5;
    const int lane = tid & 31;
    const int g    = lane >> 2;         // 0..7
    const int t    = lane & 3;          // 0..3
    const int warpM = wid & 3;          // 0..3  -> m offset *32
    const int warpN = wid >> 2;         // 0..1  -> n offset *64

    const int by  = blockIdx.y;
    const bool isq = by < 16;
    const int bm  = (isq ? by : by - 16) * 128;
    const int bn  = blockIdx.x * 128;

    const __nv_bfloat16* Ah = isq ? g_sh  : g_kh;
    const __nv_bfloat16* Al = isq ? g_sl  : g_kl;
    const __nv_bfloat16* Wh = isq ? g_qwh : g_kwh;
    const __nv_bfloat16* Wl = isq ? g_qwl : g_kwl;
    const float*       bias = isq ? q_b   : k_b;
    float*                C = isq ? g_q   : g_k;

    float4 acc[2][8];
#pragma unroll
    for (int i = 0; i < 2; i++)
#pragma unroll
        for (int j = 0; j < 8; j++) acc[i][j] = make_float4(0.f, 0.f, 0.f, 0.f);

    const uint32_t smem_base = smem_u32(smem);

    // cp.async one chunk (4 tiles) into buffer `buf`
    // per tile: 128 rows x 64B = 512 x 16B segments; 256 threads -> 2 each
    auto load_chunk = [&](int c, int buf) {
        const int k0 = c * CK;
        const uint32_t sb = smem_base + buf * BUF_BYTES;
#pragma unroll
        for (int h = 0; h < 2; h++) {
            int seg = tid + h * 256;        // 0..511
            int row = seg >> 2;             // 0..127
            int s4  = seg & 3;              // 16B segment within 64B row
            uint32_t soff = (uint32_t)(row * STR + s4 * 8) * 2;   // bytes
            size_t ga = (size_t)(bm + row) * D_DIM + k0 + s4 * 8;
            size_t gw = (size_t)(bn + row) * D_DIM + k0 + s4 * 8;
            cp_async16(sb + soff,                Ah + ga);
            cp_async16(sb + TILE_BYTES   + soff, Al + ga);
            cp_async16(sb + 2*TILE_BYTES + soff, Wh + gw);
            cp_async16(sb + 3*TILE_BYTES + soff, Wl + gw);
        }
        cp_async_commit();
    };

    load_chunk(0, 0);
    cp_async_wait0();
    __syncthreads();

    for (int c = 0; c < NCH; c++) {
        const int buf = c & 1;
        if (c + 1 < NCH) load_chunk(c + 1, buf ^ 1);

        const char* tb  = smem + buf * BUF_BYTES;
        const __nv_bfloat16* sAh = (const __nv_bfloat16*)tb;
        const __nv_bfloat16* sAl = (const __nv_bfloat16*)(tb + TILE_BYTES);
        const __nv_bfloat16* sWh = (const __nv_bfloat16*)(tb + 2*TILE_BYTES);
        const __nv_bfloat16* sWl = (const __nv_bfloat16*)(tb + 3*TILE_BYTES);

#pragma unroll
        for (int ks = 0; ks < CK; ks += 16) {
            // A fragments (hi & lo) for 2 m-frags
            uint32_t ah[2][4], al[2][4];
#pragma unroll
            for (int i = 0; i < 2; i++) {
                int r0 = warpM * 32 + i * 16 + g;
                const __nv_bfloat16* p0 = sAh + r0 * STR + ks + 2 * t;
                const __nv_bfloat16* p1 = sAh + (r0 + 8) * STR + ks + 2 * t;
                ah[i][0] = *(const uint32_t*)p0;
                ah[i][1] = *(const uint32_t*)p1;
                ah[i][2] = *(const uint32_t*)(p0 + 8);
                ah[i][3] = *(const uint32_t*)(p1 + 8);
                const __nv_bfloat16* q0 = sAl + r0 * STR + ks + 2 * t;
                const __nv_bfloat16* q1 = sAl + (r0 + 8) * STR + ks + 2 * t;
                al[i][0] = *(const uint32_t*)q0;
                al[i][1] = *(const uint32_t*)q1;
                al[i][2] = *(const uint32_t*)(q0 + 8);
                al[i][3] = *(const uint32_t*)(q1 + 8);
            }
#pragma unroll
            for (int j = 0; j < 8; j++) {
                int rw = warpN * 64 + j * 8 + g;
                const __nv_bfloat16* pw = sWh + rw * STR + ks + 2 * t;
                uint32_t bh0 = *(const uint32_t*)pw;
                uint32_t bh1 = *(const uint32_t*)(pw + 8);
                const __nv_bfloat16* pl = sWl + rw * STR + ks + 2 * t;
                uint32_t bl0 = *(const uint32_t*)pl;
                uint32_t bl1 = *(const uint32_t*)(pl + 8);
#pragma unroll
                for (int i = 0; i < 2; i++) {
                    mma16816(acc[i][j], ah[i][0], ah[i][1], ah[i][2], ah[i][3], bh0, bh1);
                    mma16816(acc[i][j], ah[i][0], ah[i][1], ah[i][2], ah[i][3], bl0, bl1);
                    mma16816(acc[i][j], al[i][0], al[i][1], al[i][2], al[i][3], bh0, bh1);
                }
            }
        }

        cp_async_wait0();
        __syncthreads();
    }

    // epilogue: bias + ReLU, fp32 out
#pragma unroll
    for (int i = 0; i < 2; i++) {
        int row0 = bm + warpM * 32 + i * 16 + g;
#pragma unroll
        for (int j = 0; j < 8; j++) {
            int col = bn + warpN * 64 + j * 8 + 2 * t;
            float b0 = bias[col], b1 = bias[col + 1];
            float2 o0, o1;
            o0.x = fmaxf(acc[i][j].x + b0, 0.f);
            o0.y = fmaxf(acc[i][j].y + b1, 0.f);
            o1.x = fmaxf(acc[i][j].z + b0, 0.f);
            o1.y = fmaxf(acc[i][j].w + b1, 0.f);
            *(float2*)(C + (size_t)row0 * D_DIM + col)       = o0;
            *(float2*)(C + (size_t)(row0 + 8) * D_DIM + col) = o1;
        }
    }
}

// ---------------------------------------------------------------------------
// Energy + sigmoid (unchanged, known-passing).
// ---------------------------------------------------------------------------
__global__ __launch_bounds__(256)
void energy_kernel(const float* __restrict__ Q, const float* __restrict__ Kp,
                   const float* __restrict__ ebias, float* __restrict__ P)
{
    __shared__ float Qs[32][65];
    __shared__ float Ks[32][130];

    const int bh = blockIdx.z;
    const int bb = bh >> 4;
    const int hh = bh & 15;
    const int m0 = blockIdx.y * 64;
    const int n0 = blockIdx.x * 128;
    const int tid = threadIdx.x;

    const float* Qbase = Q + (size_t)bb * TGT * D_DIM + hh * DH;
    const float* Kbase = Kp + (size_t)bb * SRC * D_DIM + hh * DH;

    const int qr = tid >> 3;
    const int qc = (tid & 7) * 4;
    const int tmr = (tid >> 4) * 4;
    const int tnc = (tid & 15) * 8;

    float2 acc[4][4];
#pragma unroll
    for (int i = 0; i < 4; i++)
#pragma unroll
        for (int j = 0; j < 4; j++) acc[i][j] = make_float2(0.f, 0.f);

    for (int k0 = 0; k0 < DH; k0 += 32) {
        float4 v0 = *(const float4*)(Qbase + (size_t)(m0 + qr) * D_DIM + k0 + qc);
        float4 v1 = *(const float4*)(Qbase + (size_t)(m0 + qr + 32) * D_DIM + k0 + qc);
        float4 w0 = *(const float4*)(Kbase + (size_t)(n0 + qr) * D_DIM + k0 + qc);
        float4 w1 = *(const float4*)(Kbase + (size_t)(n0 + qr + 32) * D_DIM + k0 + qc);
        float4 w2 = *(const float4*)(Kbase + (size_t)(n0 + qr + 64) * D_DIM + k0 + qc);
        float4 w3 = *(const float4*)(Kbase + (size_t)(n0 + qr + 96) * D_DIM + k0 + qc);
        __syncthreads();
        Qs[qc+0][qr] = v0.x; Qs[qc+1][qr] = v0.y; Qs[qc+2][qr] = v0.z; Qs[qc+3][qr] = v0.w;
        Qs[qc+0][qr+32] = v1.x; Qs[qc+1][qr+32] = v1.y; Qs[qc+2][qr+32] = v1.z; Qs[qc+3][qr+32] = v1.w;
        Ks[qc+0][qr] = w0.x; Ks[qc+1][qr] = w0.y; Ks[qc+2][qr] = w0.z; Ks[qc+3][qr] = w0.w;
        Ks[qc+0][qr+32] = w1.x; Ks[qc+1][qr+32] = w1.y; Ks[qc+2][qr+32] = w1.z; Ks[qc+3][qr+32] = w1.w;
        Ks[qc+0][qr+64] = w2.x; Ks[qc+1][qr+64] = w2.y; Ks[qc+2][qr+64] = w2.z; Ks[qc+3][qr+64] = w2.w;
        Ks[qc+0][qr+96] = w3.x; Ks[qc+1][qr+96] = w3.y; Ks[qc+2][qr+96] = w3.z; Ks[qc+3][qr+96] = w3.w;
        __syncthreads();
#pragma unroll
        for (int kk = 0; kk < 32; kk++) {
            float ra[4];
            float2 rb[4];
#pragma unroll
            for (int i = 0; i < 4; i++) ra[i] = Qs[kk][tmr + i];
#pragma unroll
            for (int j = 0; j < 4; j++) rb[j] = *(const float2*)&Ks[kk][tnc + 2*j];
#pragma unroll
            for (int i = 0; i < 4; i++) {
                float2 a2 = make_float2(ra[i], ra[i]);
#pragma unroll
                for (int j = 0; j < 4; j++) fma2(acc[i][j], a2, rb[j]);
            }
        }
    }

    const float eb5 = ebias[0] * 5.0f;

#pragma unroll
    for (int i = 0; i < 4; i++) {
        float e[8];
        e[0]=acc[i][0].x; e[1]=acc[i][0].y; e[2]=acc[i][1].x; e[3]=acc[i][1].y;
        e[4]=acc[i][2].x; e[5]=acc[i][2].y; e[6]=acc[i][3].x; e[7]=acc[i][3].y;
        float4 o0, o1;
#pragma unroll
        for (int j = 0; j < 8; j++) {
            float z = fmaf(e[j], 0.625f, eb5);
            float pv = 1.0f / (1.0f + __expf(-z));
            if (j < 4) ((float*)&o0)[j] = pv; else ((float*)&o1)[j-4] = pv;
        }
        float* dst = P + ((size_t)bh * TGT + (m0 + tmr + i)) * SRC + n0 + tnc;
        *(float4*)(dst)     = o0;
        *(float4*)(dst + 4) = o1;
    }
}

// ---------------------------------------------------------------------------
// Monotonic alignment (unchanged v2, known-passing).
// ---------------------------------------------------------------------------
__global__ __launch_bounds__(32)
void alpha_kernel(const float* __restrict__ p, float* __restrict__ alpha)
{
    const int lane = threadIdx.x;
    const int bh   = blockIdx.x;

    const float4* pr = (const float4*)(p     + (size_t)bh * TGT * SRC + lane * 16);
    float4*       ar = (float4*)      (alpha + (size_t)bh * TGT * SRC + lane * 16);

    float4 buf[2][4];
#pragma unroll
    for (int j = 0; j < 4; j++) buf[0][j] = __ldcs(pr + j);
#pragma unroll
    for (int j = 0; j < 4; j++) buf[1][j] = __ldcs(pr + 128 + j);

    float Bv[16];
#pragma unroll
    for (int j = 0; j < 16; j++) Bv[j] = 0.f;
    if (lane == 0) Bv[0] = 1.f;

    float pc[16], Av[16], Pa[16];
    float m1, m2, m4, m8, m16;
    {
#pragma unroll
        for (int j = 0; j < 4; j++) {
            pc[4*j+0] = buf[0][j].x; pc[4*j+1] = buf[0][j].y;
            pc[4*j+2] = buf[0][j].z; pc[4*j+3] = buf[0][j].w;
        }
        float prevlast = __shfl_up_sync(0xffffffffu, pc[15], 1);
        Av[0] = (lane == 0) ? 0.f : (1.f - prevlast);
#pragma unroll
        for (int j = 1; j < 16; j++) Av[j] = 1.f - pc[j-1];
        Pa[0] = Av[0];
#pragma unroll
        for (int j = 1; j < 16; j++) Pa[j] = Pa[j-1] * Av[j];
        m1  = Pa[15];
        m2  = m1 * __shfl_up_sync(0xffffffffu, m1, 1);
        m4  = m2 * __shfl_up_sync(0xffffffffu, m2, 2);
        m8  = m4 * __shfl_up_sync(0xffffffffu, m4, 4);
        m16 = m8 * __shfl_up_sync(0xffffffffu, m8, 8);
    }

    for (int i = 0; i < TGT; i++) {
        if (i + 2 < TGT) {
            float4* bslot = buf[i & 1];
#pragma unroll
            for (int j = 0; j < 4; j++) bslot[j] = __ldcs(pr + (size_t)(i + 2) * 128 + j);
        }

        float Pb[16];
        Pb[0] = Bv[0];
#pragma unroll
        for (int j = 1; j < 16; j++) Pb[j] = fmaf(Pb[j-1], Av[j], Bv[j]);

        float b = Pb[15];
        {
            float tt;
            tt = __shfl_up_sync(0xffffffffu, b, 1);  if (lane >= 1)  b = fmaf(tt, m1,  b);
            tt = __shfl_up_sync(0xffffffffu, b, 2);  if (lane >= 2)  b = fmaf(tt, m2,  b);
            tt = __shfl_up_sync(0xffffffffu, b, 4);  if (lane >= 4)  b = fmaf(tt, m4,  b);
            tt = __shfl_up_sync(0xffffffffu, b, 8);  if (lane >= 8)  b = fmaf(tt, m8,  b);
            tt = __shfl_up_sync(0xffffffffu, b, 16); if (lane >= 16) b = fmaf(tt, m16, b);
        }
        float qin = __shfl_up_sync(0xffffffffu, b, 1);
        if (lane == 0) qin = 0.f;

        float al[16];
#pragma unroll
        for (int j = 0; j < 16; j++) {
            float q = fmaf(qin, Pa[j], Pb[j]);
            al[j] = pc[j] * q;
            Bv[j] = al[j];
        }

        __stcs(ar + (size_t)i * 128 + 0, make_float4(al[0],  al[1],  al[2],  al[3]));
        __stcs(ar + (size_t)i * 128 + 1, make_float4(al[4],  al[5],  al[6],  al[7]));
        __stcs(ar + (size_t)i * 128 + 2, make_float4(al[8],  al[9],  al[10], al[11]));
        __stcs(ar + (size_t)i * 128 + 3, make_float4(al[12], al[13], al[14], al[15]));

        if (i + 1 < TGT) {
            const float4* bslot = buf[(i + 1) & 1];
#pragma unroll
            for (int j = 0; j < 4; j++) {
                pc[4*j+0] = bslot[j].x; pc[4*j+1] = bslot[j].y;
                pc[4*j+2] = bslot[j].z; pc[4*j+3] = bslot[j].w;
            }
            float prevlast = __shfl_up_sync(0xffffffffu, pc[15], 1);
            Av[0] = (lane == 0) ? 0.f : (1.f - prevlast);
#pragma unroll
            for (int j = 1; j < 16; j++) Av[j] = 1.f - pc[j-1];
            Pa[0] = Av[0];
#pragma unroll
            for (int j = 1; j < 16; j++) Pa[j] = Pa[j-1] * Av[j];
            m1  = Pa[15];
            m2  = m1 * __shfl_up_sync(0xffffffffu, m1, 1);
            m4  = m2 * __shfl_up_sync(0xffffffffu, m2, 2);
            m8  = m4 * __shfl_up_sync(0xffffffffu, m4, 4);
            m16 = m8 * __shfl_up_sync(0xffffffffu, m8, 8);
        }
    }
}

// ---------------------------------------------------------------------------
extern "C" void kernel_launch(void* const* d_in, const int* in_sizes, int n_in,
                              void* d_out, int out_size)
{
    const float* seqs  = (const float*)d_in[0];
    const float* keys  = (const float*)d_in[1];
    const float* q_w   = (const float*)d_in[2];
    const float* q_b   = (const float*)d_in[3];
    const float* k_w   = (const float*)d_in[4];
    const float* k_b   = (const float*)d_in[5];
    const float* ebias = (const float*)d_in[6];

    float* p_out = (float*)d_out;
    float* a_out = p_out + P_ELEMS;

    float* gq;  cudaGetSymbolAddress((void**)&gq,  g_q);
    float* gk;  cudaGetSymbolAddress((void**)&gk,  g_k);
    void *sh, *sl, *kh, *kl, *qwh, *qwl, *kwh, *kwl;
    cudaGetSymbolAddress(&sh,  g_sh);  cudaGetSymbolAddress(&sl,  g_sl);
    cudaGetSymbolAddress(&kh,  g_kh);  cudaGetSymbolAddress(&kl,  g_kl);
    cudaGetSymbolAddress(&qwh, g_qwh); cudaGetSymbolAddress(&qwl, g_qwl);
    cudaGetSymbolAddress(&kwh, g_kwh); cudaGetSymbolAddress(&kwl, g_kwl);

    cudaFuncSetAttribute(proj_mma, cudaFuncAttributeMaxDynamicSharedMemorySize, PROJ_SMEM);

    cvt_kernel<<<(MQ*D_DIM/4 + 255)/256, 256>>>((const float4*)seqs, (ushort4*)sh, (ushort4*)sl, MQ*D_DIM/4);
    cvt_kernel<<<(MK*D_DIM/4 + 255)/256, 256>>>((const float4*)keys, (ushort4*)kh, (ushort4*)kl, MK*D_DIM/4);
    cvt_kernel<<<(D_DIM*D_DIM/4 + 255)/256, 256>>>((const float4*)q_w, (ushort4*)qwh, (ushort4*)qwl, D_DIM*D_DIM/4);
    cvt_kernel<<<(D_DIM*D_DIM/4 + 255)/256, 256>>>((const float4*)k_w, (ushort4*)kwh, (ushort4*)kwl, D_DIM*D_DIM/4);

    proj_mma<<<dim3(8, 48), 256, PROJ_SMEM>>>(q_b, k_b);
    energy_kernel<<<dim3(4, 4, BH), 256>>>(gq, gk, ebias, p_out);
    alpha_kernel<<<BH, 32>>>(p_out, a_out);
}

// round 5
// speedup vs baseline: 1.5849x; 1.1441x over previous
#include <cuda_runtime.h>
#include <cuda_bf16.h>
#include <cstdint>

// ---------------------------------------------------------------------------
// B=8, TGT=256, SRC=512, D=1024, H=16, dh=64, TEMP=0.2
// Output: p_choose (8,16,256,512) then alpha (8,16,256,512), fp32.
// ---------------------------------------------------------------------------

#define D_DIM   1024
#define TGT     256
#define SRC     512
#define NB      8
#define NH      16
#define DH      64
#define BH      (NB*NH)
#define P_ELEMS ((size_t)BH*TGT*SRC)

#define MQ (NB*TGT)     // 2048
#define MK (NB*SRC)     // 4096

// bf16 hi/lo decompositions of inputs
__device__ __nv_bfloat16 g_sh[MQ*D_DIM], g_sl[MQ*D_DIM];
__device__ __nv_bfloat16 g_kh[MK*D_DIM], g_kl[MK*D_DIM];
__device__ __nv_bfloat16 g_qwh[D_DIM*D_DIM], g_qwl[D_DIM*D_DIM];
__device__ __nv_bfloat16 g_kwh[D_DIM*D_DIM], g_kwl[D_DIM*D_DIM];
// bf16 hi/lo activations (projection outputs, written by proj epilogue)
__device__ __nv_bfloat16 g_aqh[MQ*D_DIM], g_aql[MQ*D_DIM];
__device__ __nv_bfloat16 g_akh[MK*D_DIM], g_akl[MK*D_DIM];

// warp-level bf16 mma (valid on compute_103 PTX; compiles to HMMA SASS)
__device__ __forceinline__ void mma16816(float4& d,
    uint32_t a0, uint32_t a1, uint32_t a2, uint32_t a3,
    uint32_t b0, uint32_t b1)
{
    asm volatile(
        "mma.sync.aligned.m16n8k16.row.col.f32.bf16.bf16.f32 "
        "{%0,%1,%2,%3}, {%4,%5,%6,%7}, {%8,%9}, {%0,%1,%2,%3};"
        : "+f"(d.x), "+f"(d.y), "+f"(d.z), "+f"(d.w)
        : "r"(a0), "r"(a1), "r"(a2), "r"(a3), "r"(b0), "r"(b1));
}

__device__ __forceinline__ void cp_async16(uint32_t smem_dst, const void* gsrc) {
    asm volatile("cp.async.ca.shared.global [%0], [%1], 16;" :: "r"(smem_dst), "l"(gsrc));
}
__device__ __forceinline__ void cp_async_commit() {
    asm volatile("cp.async.commit_group;" ::: "memory");
}
__device__ __forceinline__ void cp_async_wait0() {
    asm volatile("cp.async.wait_group 0;" ::: "memory");
}
__device__ __forceinline__ uint32_t smem_u32(const void* p) {
    uint32_t a;
    asm("{ .reg .u64 t; cvta.to.shared.u64 t, %1; cvt.u32.u64 %0, t; }" : "=r"(a) : "l"(p));
    return a;
}

// ---------------------------------------------------------------------------
// fp32 -> (hi, lo) bf16 decomposition.
// ---------------------------------------------------------------------------
__global__ __launch_bounds__(256)
void cvt_kernel(const float4* __restrict__ in, ushort4* __restrict__ hi,
                ushort4* __restrict__ lo, int n4)
{
    int i = blockIdx.x * 256 + threadIdx.x;
    if (i >= n4) return;
    float4 v = in[i];
    ushort4 h, l;
    {
        __nv_bfloat16 hb = __float2bfloat16(v.x);
        __nv_bfloat16 lb = __float2bfloat16(v.x - __bfloat162float(hb));
        h.x = *(unsigned short*)&hb; l.x = *(unsigned short*)&lb;
    }
    {
        __nv_bfloat16 hb = __float2bfloat16(v.y);
        __nv_bfloat16 lb = __float2bfloat16(v.y - __bfloat162float(hb));
        h.y = *(unsigned short*)&hb; l.y = *(unsigned short*)&lb;
    }
    {
        __nv_bfloat16 hb = __float2bfloat16(v.z);
        __nv_bfloat16 lb = __float2bfloat16(v.z - __bfloat162float(hb));
        h.z = *(unsigned short*)&hb; l.z = *(unsigned short*)&lb;
    }
    {
        __nv_bfloat16 hb = __float2bfloat16(v.w);
        __nv_bfloat16 lb = __float2bfloat16(v.w - __bfloat162float(hb));
        h.w = *(unsigned short*)&hb; l.w = *(unsigned short*)&lb;
    }
    hi[i] = h; lo[i] = l;
}

// ---------------------------------------------------------------------------
// mma.sync bf16-split projection GEMM + bias + ReLU -> bf16 hi/lo activations.
// CTA tile 128x128, 8 warps (4M x 2N), warp tile 32x64. K chunk 32, cp.async x2.
// ---------------------------------------------------------------------------
#define CK      32
#define NCH     (D_DIM/CK)            // 32
#define STR     40
#define TILE_BYTES (128*STR*2)        // 10240
#define BUF_BYTES  (4*TILE_BYTES)     // 40960
#define PROJ_SMEM  (2*BUF_BYTES)      // 81920

__global__ __launch_bounds__(256)
void proj_mma(const float* __restrict__ q_b, const float* __restrict__ k_b)
{
    extern __shared__ char smem[];
    const int tid  = threadIdx.x;
    const int wid  = tid >> 5;
    const int lane = tid & 31;
    const int g    = lane >> 2;
    const int t    = lane & 3;
    const int warpM = wid & 3;
    const int warpN = wid >> 2;

    const int by  = blockIdx.y;
    const bool isq = by < 16;
    const int bm  = (isq ? by : by - 16) * 128;
    const int bn  = blockIdx.x * 128;

    const __nv_bfloat16* Ah = isq ? g_sh  : g_kh;
    const __nv_bfloat16* Al = isq ? g_sl  : g_kl;
    const __nv_bfloat16* Wh = isq ? g_qwh : g_kwh;
    const __nv_bfloat16* Wl = isq ? g_qwl : g_kwl;
    const float*       bias = isq ? q_b   : k_b;
    __nv_bfloat16*       CH = isq ? g_aqh : g_akh;
    __nv_bfloat16*       CL = isq ? g_aql : g_akl;

    float4 acc[2][8];
#pragma unroll
    for (int i = 0; i < 2; i++)
#pragma unroll
        for (int j = 0; j < 8; j++) acc[i][j] = make_float4(0.f, 0.f, 0.f, 0.f);

    const uint32_t smem_base = smem_u32(smem);

    auto load_chunk = [&](int c, int buf) {
        const int k0 = c * CK;
        const uint32_t sb = smem_base + buf * BUF_BYTES;
#pragma unroll
        for (int h = 0; h < 2; h++) {
            int seg = tid + h * 256;
            int row = seg >> 2;
            int s4  = seg & 3;
            uint32_t soff = (uint32_t)(row * STR + s4 * 8) * 2;
            size_t ga = (size_t)(bm + row) * D_DIM + k0 + s4 * 8;
            size_t gw = (size_t)(bn + row) * D_DIM + k0 + s4 * 8;
            cp_async16(sb + soff,                Ah + ga);
            cp_async16(sb + TILE_BYTES   + soff, Al + ga);
            cp_async16(sb + 2*TILE_BYTES + soff, Wh + gw);
            cp_async16(sb + 3*TILE_BYTES + soff, Wl + gw);
        }
        cp_async_commit();
    };

    load_chunk(0, 0);
    cp_async_wait0();
    __syncthreads();

    for (int c = 0; c < NCH; c++) {
        const int buf = c & 1;
        if (c + 1 < NCH) load_chunk(c + 1, buf ^ 1);

        const char* tb  = smem + buf * BUF_BYTES;
        const __nv_bfloat16* sAh = (const __nv_bfloat16*)tb;
        const __nv_bfloat16* sAl = (const __nv_bfloat16*)(tb + TILE_BYTES);
        const __nv_bfloat16* sWh = (const __nv_bfloat16*)(tb + 2*TILE_BYTES);
        const __nv_bfloat16* sWl = (const __nv_bfloat16*)(tb + 3*TILE_BYTES);

#pragma unroll
        for (int ks = 0; ks < CK; ks += 16) {
            uint32_t ah[2][4], al[2][4];
#pragma unroll
            for (int i = 0; i < 2; i++) {
                int r0 = warpM * 32 + i * 16 + g;
                const __nv_bfloat16* p0 = sAh + r0 * STR + ks + 2 * t;
                const __nv_bfloat16* p1 = sAh + (r0 + 8) * STR + ks + 2 * t;
                ah[i][0] = *(const uint32_t*)p0;
                ah[i][1] = *(const uint32_t*)p1;
                ah[i][2] = *(const uint32_t*)(p0 + 8);
                ah[i][3] = *(const uint32_t*)(p1 + 8);
                const __nv_bfloat16* q0 = sAl + r0 * STR + ks + 2 * t;
                const __nv_bfloat16* q1 = sAl + (r0 + 8) * STR + ks + 2 * t;
                al[i][0] = *(const uint32_t*)q0;
                al[i][1] = *(const uint32_t*)q1;
                al[i][2] = *(const uint32_t*)(q0 + 8);
                al[i][3] = *(const uint32_t*)(q1 + 8);
            }
#pragma unroll
            for (int j = 0; j < 8; j++) {
                int rw = warpN * 64 + j * 8 + g;
                const __nv_bfloat16* pw = sWh + rw * STR + ks + 2 * t;
                uint32_t bh0 = *(const uint32_t*)pw;
                uint32_t bh1 = *(const uint32_t*)(pw + 8);
                const __nv_bfloat16* pl = sWl + rw * STR + ks + 2 * t;
                uint32_t bl0 = *(const uint32_t*)pl;
                uint32_t bl1 = *(const uint32_t*)(pl + 8);
#pragma unroll
                for (int i = 0; i < 2; i++) {
                    mma16816(acc[i][j], ah[i][0], ah[i][1], ah[i][2], ah[i][3], bh0, bh1);
                    mma16816(acc[i][j], ah[i][0], ah[i][1], ah[i][2], ah[i][3], bl0, bl1);
                    mma16816(acc[i][j], al[i][0], al[i][1], al[i][2], al[i][3], bh0, bh1);
                }
            }
        }

        cp_async_wait0();
        __syncthreads();
    }

    // epilogue: bias + ReLU -> bf16 hi/lo
#pragma unroll
    for (int i = 0; i < 2; i++) {
        int row0 = bm + warpM * 32 + i * 16 + g;
#pragma unroll
        for (int j = 0; j < 8; j++) {
            int col = bn + warpN * 64 + j * 8 + 2 * t;
            float b0 = bias[col], b1 = bias[col + 1];
            float v[4];
            v[0] = fmaxf(acc[i][j].x + b0, 0.f);
            v[1] = fmaxf(acc[i][j].y + b1, 0.f);
            v[2] = fmaxf(acc[i][j].z + b0, 0.f);
            v[3] = fmaxf(acc[i][j].w + b1, 0.f);
            __nv_bfloat16 h[4], l[4];
#pragma unroll
            for (int u = 0; u < 4; u++) {
                h[u] = __float2bfloat16(v[u]);
                l[u] = __float2bfloat16(v[u] - __bfloat162float(h[u]));
            }
            __nv_bfloat162 h01; h01.x = h[0]; h01.y = h[1];
            __nv_bfloat162 h23; h23.x = h[2]; h23.y = h[3];
            __nv_bfloat162 l01; l01.x = l[0]; l01.y = l[1];
            __nv_bfloat162 l23; l23.x = l[2]; l23.y = l[3];
            *(__nv_bfloat162*)(CH + (size_t)row0 * D_DIM + col)       = h01;
            *(__nv_bfloat162*)(CH + (size_t)(row0 + 8) * D_DIM + col) = h23;
            *(__nv_bfloat162*)(CL + (size_t)row0 * D_DIM + col)       = l01;
            *(__nv_bfloat162*)(CL + (size_t)(row0 + 8) * D_DIM + col) = l23;
        }
    }
}

// ---------------------------------------------------------------------------
// mma.sync bf16-split energy + sigmoid.
// Per (b,h): E = Qa(256x64) @ Ka(512x64)^T ; p = sigmoid(E*0.625 + eb*5).
// CTA tile 128(M) x 128(N), K=64 single shot. 8 warps (4M x 2N).
// Grid: (4 n-tiles, 2 m-tiles, 128 bh).
// ---------------------------------------------------------------------------
#define ESTR    72
#define ETILE_BYTES (128*ESTR*2)      // 18432
#define E_SMEM  (4*ETILE_BYTES)       // 73728

__global__ __launch_bounds__(256)
void energy_mma(const float* __restrict__ ebias, float* __restrict__ P)
{
    extern __shared__ char smem[];
    const int tid  = threadIdx.x;
    const int wid  = tid >> 5;
    const int lane = tid & 31;
    const int g    = lane >> 2;
    const int t    = lane & 3;
    const int warpM = wid & 3;
    const int warpN = wid >> 2;

    const int bh = blockIdx.z;
    const int bb = bh >> 4;
    const int hh = bh & 15;
    const int m0 = blockIdx.y * 128;
    const int n0 = blockIdx.x * 128;

    const __nv_bfloat16* Qh = g_aqh + (size_t)bb * TGT * D_DIM + hh * DH;
    const __nv_bfloat16* Ql = g_aql + (size_t)bb * TGT * D_DIM + hh * DH;
    const __nv_bfloat16* Kh = g_akh + (size_t)bb * SRC * D_DIM + hh * DH;
    const __nv_bfloat16* Kl = g_akl + (size_t)bb * SRC * D_DIM + hh * DH;

    const uint32_t sb = smem_u32(smem);

    // load 4 tiles of 128 rows x 64 bf16 (8 x 16B segs per row)
    // tile order: Qh, Ql, Kh, Kl
#pragma unroll
    for (int h = 0; h < 4; h++) {
        int seg = tid + h * 256;          // 0..1023
        int row = seg >> 3;               // 0..127
        int s   = seg & 7;                // 16B segment
        uint32_t soff = (uint32_t)(row * ESTR + s * 8) * 2;
        cp_async16(sb + soff,                 Qh + (size_t)(m0 + row) * D_DIM + s * 8);
        cp_async16(sb + ETILE_BYTES   + soff, Ql + (size_t)(m0 + row) * D_DIM + s * 8);
        cp_async16(sb + 2*ETILE_BYTES + soff, Kh + (size_t)(n0 + row) * D_DIM + s * 8);
        cp_async16(sb + 3*ETILE_BYTES + soff, Kl + (size_t)(n0 + row) * D_DIM + s * 8);
    }
    cp_async_commit();
    cp_async_wait0();
    __syncthreads();

    const __nv_bfloat16* sQh = (const __nv_bfloat16*)smem;
    const __nv_bfloat16* sQl = (const __nv_bfloat16*)(smem + ETILE_BYTES);
    const __nv_bfloat16* sKh = (const __nv_bfloat16*)(smem + 2*ETILE_BYTES);
    const __nv_bfloat16* sKl = (const __nv_bfloat16*)(smem + 3*ETILE_BYTES);

    float4 acc[2][8];
#pragma unroll
    for (int i = 0; i < 2; i++)
#pragma unroll
        for (int j = 0; j < 8; j++) acc[i][j] = make_float4(0.f, 0.f, 0.f, 0.f);

#pragma unroll
    for (int ks = 0; ks < DH; ks += 16) {
        uint32_t ah[2][4], al[2][4];
#pragma unroll
        for (int i = 0; i < 2; i++) {
            int r0 = warpM * 32 + i * 16 + g;
            const __nv_bfloat16* p0 = sQh + r0 * ESTR + ks + 2 * t;
            const __nv_bfloat16* p1 = sQh + (r0 + 8) * ESTR + ks + 2 * t;
            ah[i][0] = *(const uint32_t*)p0;
            ah[i][1] = *(const uint32_t*)p1;
            ah[i][2] = *(const uint32_t*)(p0 + 8);
            ah[i][3] = *(const uint32_t*)(p1 + 8);
            const __nv_bfloat16* q0 = sQl + r0 * ESTR + ks + 2 * t;
            const __nv_bfloat16* q1 = sQl + (r0 + 8) * ESTR + ks + 2 * t;
            al[i][0] = *(const uint32_t*)q0;
            al[i][1] = *(const uint32_t*)q1;
            al[i][2] = *(const uint32_t*)(q0 + 8);
            al[i][3] = *(const uint32_t*)(q1 + 8);
        }
#pragma unroll
        for (int j = 0; j < 8; j++) {
            int rw = warpN * 64 + j * 8 + g;
            const __nv_bfloat16* pw = sKh + rw * ESTR + ks + 2 * t;
            uint32_t bh0 = *(const uint32_t*)pw;
            uint32_t bh1 = *(const uint32_t*)(pw + 8);
            const __nv_bfloat16* pl = sKl + rw * ESTR + ks + 2 * t;
            uint32_t bl0 = *(const uint32_t*)pl;
            uint32_t bl1 = *(const uint32_t*)(pl + 8);
#pragma unroll
            for (int i = 0; i < 2; i++) {
                mma16816(acc[i][j], ah[i][0], ah[i][1], ah[i][2], ah[i][3], bh0, bh1);
                mma16816(acc[i][j], ah[i][0], ah[i][1], ah[i][2], ah[i][3], bl0, bl1);
                mma16816(acc[i][j], al[i][0], al[i][1], al[i][2], al[i][3], bh0, bh1);
            }
        }
    }

    const float eb5 = ebias[0] * 5.0f;   // z = E*0.625 + eb*5

#pragma unroll
    for (int i = 0; i < 2; i++) {
        int row0 = m0 + warpM * 32 + i * 16 + g;
#pragma unroll
        for (int j = 0; j < 8; j++) {
            int col = n0 + warpN * 64 + j * 8 + 2 * t;
            float z0 = fmaf(acc[i][j].x, 0.625f, eb5);
            float z1 = fmaf(acc[i][j].y, 0.625f, eb5);
            float z2 = fmaf(acc[i][j].z, 0.625f, eb5);
            float z3 = fmaf(acc[i][j].w, 0.625f, eb5);
            float2 o0, o1;
            o0.x = 1.0f / (1.0f + __expf(-z0));
            o0.y = 1.0f / (1.0f + __expf(-z1));
            o1.x = 1.0f / (1.0f + __expf(-z2));
            o1.y = 1.0f / (1.0f + __expf(-z3));
            float* dst0 = P + ((size_t)bh * TGT + row0) * SRC + col;
            float* dst1 = P + ((size_t)bh * TGT + row0 + 8) * SRC + col;
            *(float2*)dst0 = o0;
            *(float2*)dst1 = o1;
        }
    }
}

// ---------------------------------------------------------------------------
// Monotonic alignment (v2, known-passing).
// ---------------------------------------------------------------------------
__global__ __launch_bounds__(32)
void alpha_kernel(const float* __restrict__ p, float* __restrict__ alpha)
{
    const int lane = threadIdx.x;
    const int bh   = blockIdx.x;

    const float4* pr = (const float4*)(p     + (size_t)bh * TGT * SRC + lane * 16);
    float4*       ar = (float4*)      (alpha + (size_t)bh * TGT * SRC + lane * 16);

    float4 buf[2][4];
#pragma unroll
    for (int j = 0; j < 4; j++) buf[0][j] = __ldcs(pr + j);
#pragma unroll
    for (int j = 0; j < 4; j++) buf[1][j] = __ldcs(pr + 128 + j);

    float Bv[16];
#pragma unroll
    for (int j = 0; j < 16; j++) Bv[j] = 0.f;
    if (lane == 0) Bv[0] = 1.f;

    float pc[16], Av[16], Pa[16];
    float m1, m2, m4, m8, m16;
    {
#pragma unroll
        for (int j = 0; j < 4; j++) {
            pc[4*j+0] = buf[0][j].x; pc[4*j+1] = buf[0][j].y;
            pc[4*j+2] = buf[0][j].z; pc[4*j+3] = buf[0][j].w;
        }
        float prevlast = __shfl_up_sync(0xffffffffu, pc[15], 1);
        Av[0] = (lane == 0) ? 0.f : (1.f - prevlast);
#pragma unroll
        for (int j = 1; j < 16; j++) Av[j] = 1.f - pc[j-1];
        Pa[0] = Av[0];
#pragma unroll
        for (int j = 1; j < 16; j++) Pa[j] = Pa[j-1] * Av[j];
        m1  = Pa[15];
        m2  = m1 * __shfl_up_sync(0xffffffffu, m1, 1);
        m4  = m2 * __shfl_up_sync(0xffffffffu, m2, 2);
        m8  = m4 * __shfl_up_sync(0xffffffffu, m4, 4);
        m16 = m8 * __shfl_up_sync(0xffffffffu, m8, 8);
    }

    for (int i = 0; i < TGT; i++) {
        if (i + 2 < TGT) {
            float4* bslot = buf[i & 1];
#pragma unroll
            for (int j = 0; j < 4; j++) bslot[j] = __ldcs(pr + (size_t)(i + 2) * 128 + j);
        }

        float Pb[16];
        Pb[0] = Bv[0];
#pragma unroll
        for (int j = 1; j < 16; j++) Pb[j] = fmaf(Pb[j-1], Av[j], Bv[j]);

        float b = Pb[15];
        {
            float tt;
            tt = __shfl_up_sync(0xffffffffu, b, 1);  if (lane >= 1)  b = fmaf(tt, m1,  b);
            tt = __shfl_up_sync(0xffffffffu, b, 2);  if (lane >= 2)  b = fmaf(tt, m2,  b);
            tt = __shfl_up_sync(0xffffffffu, b, 4);  if (lane >= 4)  b = fmaf(tt, m4,  b);
            tt = __shfl_up_sync(0xffffffffu, b, 8);  if (lane >= 8)  b = fmaf(tt, m8,  b);
            tt = __shfl_up_sync(0xffffffffu, b, 16); if (lane >= 16) b = fmaf(tt, m16, b);
        }
        float qin = __shfl_up_sync(0xffffffffu, b, 1);
        if (lane == 0) qin = 0.f;

        float al[16];
#pragma unroll
        for (int j = 0; j < 16; j++) {
            float q = fmaf(qin, Pa[j], Pb[j]);
            al[j] = pc[j] * q;
            Bv[j] = al[j];
        }

        __stcs(ar + (size_t)i * 128 + 0, make_float4(al[0],  al[1],  al[2],  al[3]));
        __stcs(ar + (size_t)i * 128 + 1, make_float4(al[4],  al[5],  al[6],  al[7]));
        __stcs(ar + (size_t)i * 128 + 2, make_float4(al[8],  al[9],  al[10], al[11]));
        __stcs(ar + (size_t)i * 128 + 3, make_float4(al[12], al[13], al[14], al[15]));

        if (i + 1 < TGT) {
            const float4* bslot = buf[(i + 1) & 1];
#pragma unroll
            for (int j = 0; j < 4; j++) {
                pc[4*j+0] = bslot[j].x; pc[4*j+1] = bslot[j].y;
                pc[4*j+2] = bslot[j].z; pc[4*j+3] = bslot[j].w;
            }
            float prevlast = __shfl_up_sync(0xffffffffu, pc[15], 1);
            Av[0] = (lane == 0) ? 0.f : (1.f - prevlast);
#pragma unroll
            for (int j = 1; j < 16; j++) Av[j] = 1.f - pc[j-1];
            Pa[0] = Av[0];
#pragma unroll
            for (int j = 1; j < 16; j++) Pa[j] = Pa[j-1] * Av[j];
            m1  = Pa[15];
            m2  = m1 * __shfl_up_sync(0xffffffffu, m1, 1);
            m4  = m2 * __shfl_up_sync(0xffffffffu, m2, 2);
            m8  = m4 * __shfl_up_sync(0xffffffffu, m4, 4);
            m16 = m8 * __shfl_up_sync(0xffffffffu, m8, 8);
        }
    }
}

// ---------------------------------------------------------------------------
extern "C" void kernel_launch(void* const* d_in, const int* in_sizes, int n_in,
                              void* d_out, int out_size)
{
    const float* seqs  = (const float*)d_in[0];
    const float* keys  = (const float*)d_in[1];
    const float* q_w   = (const float*)d_in[2];
    const float* q_b   = (const float*)d_in[3];
    const float* k_w   = (const float*)d_in[4];
    const float* k_b   = (const float*)d_in[5];
    const float* ebias = (const float*)d_in[6];

    float* p_out = (float*)d_out;
    float* a_out = p_out + P_ELEMS;

    void *sh, *sl, *kh, *kl, *qwh, *qwl, *kwh, *kwl;
    cudaGetSymbolAddress(&sh,  g_sh);  cudaGetSymbolAddress(&sl,  g_sl);
    cudaGetSymbolAddress(&kh,  g_kh);  cudaGetSymbolAddress(&kl,  g_kl);
    cudaGetSymbolAddress(&qwh, g_qwh); cudaGetSymbolAddress(&qwl, g_qwl);
    cudaGetSymbolAddress(&kwh, g_kwh); cudaGetSymbolAddress(&kwl, g_kwl);

    cudaFuncSetAttribute(proj_mma,   cudaFuncAttributeMaxDynamicSharedMemorySize, PROJ_SMEM);
    cudaFuncSetAttribute(energy_mma, cudaFuncAttributeMaxDynamicSharedMemorySize, E_SMEM);

    cvt_kernel<<<(MQ*D_DIM/4 + 255)/256, 256>>>((const float4*)seqs, (ushort4*)sh, (ushort4*)sl, MQ*D_DIM/4);
    cvt_kernel<<<(MK*D_DIM/4 + 255)/256, 256>>>((const float4*)keys, (ushort4*)kh, (ushort4*)kl, MK*D_DIM/4);
    cvt_kernel<<<(D_DIM*D_DIM/4 + 255)/256, 256>>>((const float4*)q_w, (ushort4*)qwh, (ushort4*)qwl, D_DIM*D_DIM/4);
    cvt_kernel<<<(D_DIM*D_DIM/4 + 255)/256, 256>>>((const float4*)k_w, (ushort4*)kwh, (ushort4*)kwl, D_DIM*D_DIM/4);

    proj_mma<<<dim3(8, 48), 256, PROJ_SMEM>>>(q_b, k_b);
    energy_mma<<<dim3(4, 2, BH), 256, E_SMEM>>>(ebias, p_out);
    alpha_kernel<<<BH, 32>>>(p_out, a_out);
}

// round 6
// speedup vs baseline: 1.6801x; 1.0601x over previous
#include <cuda_runtime.h>
#include <cuda_bf16.h>
#include <cstdint>

// ---------------------------------------------------------------------------
// B=8, TGT=256, SRC=512, D=1024, H=16, dh=64, TEMP=0.2
// Output: p_choose (8,16,256,512) then alpha (8,16,256,512), fp32.
// ---------------------------------------------------------------------------

#define D_DIM   1024
#define TGT     256
#define SRC     512
#define NB      8
#define NH      16
#define DH      64
#define BH      (NB*NH)
#define P_ELEMS ((size_t)BH*TGT*SRC)

#define MQ (NB*TGT)     // 2048
#define MK (NB*SRC)     // 4096

// bf16 hi/lo decompositions of inputs
__device__ __nv_bfloat16 g_sh[MQ*D_DIM], g_sl[MQ*D_DIM];
__device__ __nv_bfloat16 g_kh[MK*D_DIM], g_kl[MK*D_DIM];
__device__ __nv_bfloat16 g_qwh[D_DIM*D_DIM], g_qwl[D_DIM*D_DIM];
__device__ __nv_bfloat16 g_kwh[D_DIM*D_DIM], g_kwl[D_DIM*D_DIM];
// bf16 hi/lo activations (projection outputs)
__device__ __nv_bfloat16 g_aqh[MQ*D_DIM], g_aql[MQ*D_DIM];
__device__ __nv_bfloat16 g_akh[MK*D_DIM], g_akl[MK*D_DIM];

__device__ __forceinline__ void mma16816(float4& d,
    uint32_t a0, uint32_t a1, uint32_t a2, uint32_t a3,
    uint32_t b0, uint32_t b1)
{
    asm volatile(
        "mma.sync.aligned.m16n8k16.row.col.f32.bf16.bf16.f32 "
        "{%0,%1,%2,%3}, {%4,%5,%6,%7}, {%8,%9}, {%0,%1,%2,%3};"
        : "+f"(d.x), "+f"(d.y), "+f"(d.z), "+f"(d.w)
        : "r"(a0), "r"(a1), "r"(a2), "r"(a3), "r"(b0), "r"(b1));
}

__device__ __forceinline__ void cp_async16(uint32_t smem_dst, const void* gsrc) {
    asm volatile("cp.async.ca.shared.global [%0], [%1], 16;" :: "r"(smem_dst), "l"(gsrc));
}
__device__ __forceinline__ void cp_async_commit() {
    asm volatile("cp.async.commit_group;" ::: "memory");
}
__device__ __forceinline__ void cp_async_wait0() {
    asm volatile("cp.async.wait_group 0;" ::: "memory");
}
__device__ __forceinline__ uint32_t smem_u32(const void* p) {
    uint32_t a;
    asm("{ .reg .u64 t; cvta.to.shared.u64 t, %1; cvt.u32.u64 %0, t; }" : "=r"(a) : "l"(p));
    return a;
}

// ---------------------------------------------------------------------------
// fp32 -> (hi, lo) bf16 decomposition.
// ---------------------------------------------------------------------------
__global__ __launch_bounds__(256)
void cvt_kernel(const float4* __restrict__ in, ushort4* __restrict__ hi,
                ushort4* __restrict__ lo, int n4)
{
    int i = blockIdx.x * 256 + threadIdx.x;
    if (i >= n4) return;
    float4 v = in[i];
    ushort4 h, l;
    {
        __nv_bfloat16 hb = __float2bfloat16(v.x);
        __nv_bfloat16 lb = __float2bfloat16(v.x - __bfloat162float(hb));
        h.x = *(unsigned short*)&hb; l.x = *(unsigned short*)&lb;
    }
    {
        __nv_bfloat16 hb = __float2bfloat16(v.y);
        __nv_bfloat16 lb = __float2bfloat16(v.y - __bfloat162float(hb));
        h.y = *(unsigned short*)&hb; l.y = *(unsigned short*)&lb;
    }
    {
        __nv_bfloat16 hb = __float2bfloat16(v.z);
        __nv_bfloat16 lb = __float2bfloat16(v.z - __bfloat162float(hb));
        h.z = *(unsigned short*)&hb; l.z = *(unsigned short*)&lb;
    }
    {
        __nv_bfloat16 hb = __float2bfloat16(v.w);
        __nv_bfloat16 lb = __float2bfloat16(v.w - __bfloat162float(hb));
        h.w = *(unsigned short*)&hb; l.w = *(unsigned short*)&lb;
    }
    hi[i] = h; lo[i] = l;
}

// ---------------------------------------------------------------------------
// mma.sync bf16-split projection GEMM + bias + ReLU -> bf16 hi/lo activations.
// (unchanged from R5 — known-passing)
// ---------------------------------------------------------------------------
#define CK      32
#define NCH     (D_DIM/CK)
#define STR     40
#define TILE_BYTES (128*STR*2)
#define BUF_BYTES  (4*TILE_BYTES)
#define PROJ_SMEM  (2*BUF_BYTES)

__global__ __launch_bounds__(256)
void proj_mma(const float* __restrict__ q_b, const float* __restrict__ k_b)
{
    extern __shared__ char smem[];
    const int tid  = threadIdx.x;
    const int wid  = tid >> 5;
    const int lane = tid & 31;
    const int g    = lane >> 2;
    const int t    = lane & 3;
    const int warpM = wid & 3;
    const int warpN = wid >> 2;

    const int by  = blockIdx.y;
    const bool isq = by < 16;
    const int bm  = (isq ? by : by - 16) * 128;
    const int bn  = blockIdx.x * 128;

    const __nv_bfloat16* Ah = isq ? g_sh  : g_kh;
    const __nv_bfloat16* Al = isq ? g_sl  : g_kl;
    const __nv_bfloat16* Wh = isq ? g_qwh : g_kwh;
    const __nv_bfloat16* Wl = isq ? g_qwl : g_kwl;
    const float*       bias = isq ? q_b   : k_b;
    __nv_bfloat16*       CH = isq ? g_aqh : g_akh;
    __nv_bfloat16*       CL = isq ? g_aql : g_akl;

    float4 acc[2][8];
#pragma unroll
    for (int i = 0; i < 2; i++)
#pragma unroll
        for (int j = 0; j < 8; j++) acc[i][j] = make_float4(0.f, 0.f, 0.f, 0.f);

    const uint32_t smem_base = smem_u32(smem);

    auto load_chunk = [&](int c, int buf) {
        const int k0 = c * CK;
        const uint32_t sb = smem_base + buf * BUF_BYTES;
#pragma unroll
        for (int h = 0; h < 2; h++) {
            int seg = tid + h * 256;
            int row = seg >> 2;
            int s4  = seg & 3;
            uint32_t soff = (uint32_t)(row * STR + s4 * 8) * 2;
            size_t ga = (size_t)(bm + row) * D_DIM + k0 + s4 * 8;
            size_t gw = (size_t)(bn + row) * D_DIM + k0 + s4 * 8;
            cp_async16(sb + soff,                Ah + ga);
            cp_async16(sb + TILE_BYTES   + soff, Al + ga);
            cp_async16(sb + 2*TILE_BYTES + soff, Wh + gw);
            cp_async16(sb + 3*TILE_BYTES + soff, Wl + gw);
        }
        cp_async_commit();
    };

    load_chunk(0, 0);
    cp_async_wait0();
    __syncthreads();

    for (int c = 0; c < NCH; c++) {
        const int buf = c & 1;
        if (c + 1 < NCH) load_chunk(c + 1, buf ^ 1);

        const char* tb  = smem + buf * BUF_BYTES;
        const __nv_bfloat16* sAh = (const __nv_bfloat16*)tb;
        const __nv_bfloat16* sAl = (const __nv_bfloat16*)(tb + TILE_BYTES);
        const __nv_bfloat16* sWh = (const __nv_bfloat16*)(tb + 2*TILE_BYTES);
        const __nv_bfloat16* sWl = (const __nv_bfloat16*)(tb + 3*TILE_BYTES);

#pragma unroll
        for (int ks = 0; ks < CK; ks += 16) {
            uint32_t ah[2][4], al[2][4];
#pragma unroll
            for (int i = 0; i < 2; i++) {
                int r0 = warpM * 32 + i * 16 + g;
                const __nv_bfloat16* p0 = sAh + r0 * STR + ks + 2 * t;
                const __nv_bfloat16* p1 = sAh + (r0 + 8) * STR + ks + 2 * t;
                ah[i][0] = *(const uint32_t*)p0;
                ah[i][1] = *(const uint32_t*)p1;
                ah[i][2] = *(const uint32_t*)(p0 + 8);
                ah[i][3] = *(const uint32_t*)(p1 + 8);
                const __nv_bfloat16* q0 = sAl + r0 * STR + ks + 2 * t;
                const __nv_bfloat16* q1 = sAl + (r0 + 8) * STR + ks + 2 * t;
                al[i][0] = *(const uint32_t*)q0;
                al[i][1] = *(const uint32_t*)q1;
                al[i][2] = *(const uint32_t*)(q0 + 8);
                al[i][3] = *(const uint32_t*)(q1 + 8);
            }
#pragma unroll
            for (int j = 0; j < 8; j++) {
                int rw = warpN * 64 + j * 8 + g;
                const __nv_bfloat16* pw = sWh + rw * STR + ks + 2 * t;
                uint32_t bh0 = *(const uint32_t*)pw;
                uint32_t bh1 = *(const uint32_t*)(pw + 8);
                const __nv_bfloat16* pl = sWl + rw * STR + ks + 2 * t;
                uint32_t bl0 = *(const uint32_t*)pl;
                uint32_t bl1 = *(const uint32_t*)(pl + 8);
#pragma unroll
                for (int i = 0; i < 2; i++) {
                    mma16816(acc[i][j], ah[i][0], ah[i][1], ah[i][2], ah[i][3], bh0, bh1);
                    mma16816(acc[i][j], ah[i][0], ah[i][1], ah[i][2], ah[i][3], bl0, bl1);
                    mma16816(acc[i][j], al[i][0], al[i][1], al[i][2], al[i][3], bh0, bh1);
                }
            }
        }

        cp_async_wait0();
        __syncthreads();
    }

#pragma unroll
    for (int i = 0; i < 2; i++) {
        int row0 = bm + warpM * 32 + i * 16 + g;
#pragma unroll
        for (int j = 0; j < 8; j++) {
            int col = bn + warpN * 64 + j * 8 + 2 * t;
            float b0 = bias[col], b1 = bias[col + 1];
            float v[4];
            v[0] = fmaxf(acc[i][j].x + b0, 0.f);
            v[1] = fmaxf(acc[i][j].y + b1, 0.f);
            v[2] = fmaxf(acc[i][j].z + b0, 0.f);
            v[3] = fmaxf(acc[i][j].w + b1, 0.f);
            __nv_bfloat16 h[4], l[4];
#pragma unroll
            for (int u = 0; u < 4; u++) {
                h[u] = __float2bfloat16(v[u]);
                l[u] = __float2bfloat16(v[u] - __bfloat162float(h[u]));
            }
            __nv_bfloat162 h01; h01.x = h[0]; h01.y = h[1];
            __nv_bfloat162 h23; h23.x = h[2]; h23.y = h[3];
            __nv_bfloat162 l01; l01.x = l[0]; l01.y = l[1];
            __nv_bfloat162 l23; l23.x = l[2]; l23.y = l[3];
            *(__nv_bfloat162*)(CH + (size_t)row0 * D_DIM + col)       = h01;
            *(__nv_bfloat162*)(CH + (size_t)(row0 + 8) * D_DIM + col) = h23;
            *(__nv_bfloat162*)(CL + (size_t)row0 * D_DIM + col)       = l01;
            *(__nv_bfloat162*)(CL + (size_t)(row0 + 8) * D_DIM + col) = l23;
        }
    }
}

// ---------------------------------------------------------------------------
// mma.sync bf16-split energy + sigmoid (unchanged from R5 — known-passing).
// ---------------------------------------------------------------------------
#define ESTR    72
#define ETILE_BYTES (128*ESTR*2)
#define E_SMEM  (4*ETILE_BYTES)

__global__ __launch_bounds__(256)
void energy_mma(const float* __restrict__ ebias, float* __restrict__ P)
{
    extern __shared__ char smem[];
    const int tid  = threadIdx.x;
    const int wid  = tid >> 5;
    const int lane = tid & 31;
    const int g    = lane >> 2;
    const int t    = lane & 3;
    const int warpM = wid & 3;
    const int warpN = wid >> 2;

    const int bh = blockIdx.z;
    const int bb = bh >> 4;
    const int hh = bh & 15;
    const int m0 = blockIdx.y * 128;
    const int n0 = blockIdx.x * 128;

    const __nv_bfloat16* Qh = g_aqh + (size_t)bb * TGT * D_DIM + hh * DH;
    const __nv_bfloat16* Ql = g_aql + (size_t)bb * TGT * D_DIM + hh * DH;
    const __nv_bfloat16* Kh = g_akh + (size_t)bb * SRC * D_DIM + hh * DH;
    const __nv_bfloat16* Kl = g_akl + (size_t)bb * SRC * D_DIM + hh * DH;

    const uint32_t sb = smem_u32(smem);

#pragma unroll
    for (int h = 0; h < 4; h++) {
        int seg = tid + h * 256;
        int row = seg >> 3;
        int s   = seg & 7;
        uint32_t soff = (uint32_t)(row * ESTR + s * 8) * 2;
        cp_async16(sb + soff,                 Qh + (size_t)(m0 + row) * D_DIM + s * 8);
        cp_async16(sb + ETILE_BYTES   + soff, Ql + (size_t)(m0 + row) * D_DIM + s * 8);
        cp_async16(sb + 2*ETILE_BYTES + soff, Kh + (size_t)(n0 + row) * D_DIM + s * 8);
        cp_async16(sb + 3*ETILE_BYTES + soff, Kl + (size_t)(n0 + row) * D_DIM + s * 8);
    }
    cp_async_commit();
    cp_async_wait0();
    __syncthreads();

    const __nv_bfloat16* sQh = (const __nv_bfloat16*)smem;
    const __nv_bfloat16* sQl = (const __nv_bfloat16*)(smem + ETILE_BYTES);
    const __nv_bfloat16* sKh = (const __nv_bfloat16*)(smem + 2*ETILE_BYTES);
    const __nv_bfloat16* sKl = (const __nv_bfloat16*)(smem + 3*ETILE_BYTES);

    float4 acc[2][8];
#pragma unroll
    for (int i = 0; i < 2; i++)
#pragma unroll
        for (int j = 0; j < 8; j++) acc[i][j] = make_float4(0.f, 0.f, 0.f, 0.f);

#pragma unroll
    for (int ks = 0; ks < DH; ks += 16) {
        uint32_t ah[2][4], al[2][4];
#pragma unroll
        for (int i = 0; i < 2; i++) {
            int r0 = warpM * 32 + i * 16 + g;
            const __nv_bfloat16* p0 = sQh + r0 * ESTR + ks + 2 * t;
            const __nv_bfloat16* p1 = sQh + (r0 + 8) * ESTR + ks + 2 * t;
            ah[i][0] = *(const uint32_t*)p0;
            ah[i][1] = *(const uint32_t*)p1;
            ah[i][2] = *(const uint32_t*)(p0 + 8);
            ah[i][3] = *(const uint32_t*)(p1 + 8);
            const __nv_bfloat16* q0 = sQl + r0 * ESTR + ks + 2 * t;
            const __nv_bfloat16* q1 = sQl + (r0 + 8) * ESTR + ks + 2 * t;
            al[i][0] = *(const uint32_t*)q0;
            al[i][1] = *(const uint32_t*)q1;
            al[i][2] = *(const uint32_t*)(q0 + 8);
            al[i][3] = *(const uint32_t*)(q1 + 8);
        }
#pragma unroll
        for (int j = 0; j < 8; j++) {
            int rw = warpN * 64 + j * 8 + g;
            const __nv_bfloat16* pw = sKh + rw * ESTR + ks + 2 * t;
            uint32_t bh0 = *(const uint32_t*)pw;
            uint32_t bh1 = *(const uint32_t*)(pw + 8);
            const __nv_bfloat16* pl = sKl + rw * ESTR + ks + 2 * t;
            uint32_t bl0 = *(const uint32_t*)pl;
            uint32_t bl1 = *(const uint32_t*)(pl + 8);
#pragma unroll
            for (int i = 0; i < 2; i++) {
                mma16816(acc[i][j], ah[i][0], ah[i][1], ah[i][2], ah[i][3], bh0, bh1);
                mma16816(acc[i][j], ah[i][0], ah[i][1], ah[i][2], ah[i][3], bl0, bl1);
                mma16816(acc[i][j], al[i][0], al[i][1], al[i][2], al[i][3], bh0, bh1);
            }
        }
    }

    const float eb5 = ebias[0] * 5.0f;

#pragma unroll
    for (int i = 0; i < 2; i++) {
        int row0 = m0 + warpM * 32 + i * 16 + g;
#pragma unroll
        for (int j = 0; j < 8; j++) {
            int col = n0 + warpN * 64 + j * 8 + 2 * t;
            float z0 = fmaf(acc[i][j].x, 0.625f, eb5);
            float z1 = fmaf(acc[i][j].y, 0.625f, eb5);
            float z2 = fmaf(acc[i][j].z, 0.625f, eb5);
            float z3 = fmaf(acc[i][j].w, 0.625f, eb5);
            float2 o0, o1;
            o0.x = 1.0f / (1.0f + __expf(-z0));
            o0.y = 1.0f / (1.0f + __expf(-z1));
            o1.x = 1.0f / (1.0f + __expf(-z2));
            o1.y = 1.0f / (1.0f + __expf(-z3));
            float* dst0 = P + ((size_t)bh * TGT + row0) * SRC + col;
            float* dst1 = P + ((size_t)bh * TGT + row0 + 8) * SRC + col;
            *(float2*)dst0 = o0;
            *(float2*)dst1 = o1;
        }
    }
}

// ---------------------------------------------------------------------------
// Monotonic alignment v3: branch-free loop, masked scan multipliers,
// split Pb chains (2x8 + combine via precomputed R).
//   q[n] = q[n-1]*A[n] + B[n],  A[n]=1-p_i[n-1] (A[0]=0), B[n]=alpha_{i-1}[n]
//   alpha_i[n] = p_i[n]*q[n]
// ---------------------------------------------------------------------------
__global__ __launch_bounds__(32)
void alpha_kernel(const float* __restrict__ p, float* __restrict__ alpha)
{
    const int lane = threadIdx.x;
    const int bh   = blockIdx.x;

    const float4* pr = (const float4*)(p     + (size_t)bh * TGT * SRC + lane * 16);
    float4*       ar = (float4*)      (alpha + (size_t)bh * TGT * SRC + lane * 16);
    // row stride = 128 float4

    float4 buf[2][4];
#pragma unroll
    for (int j = 0; j < 4; j++) buf[0][j] = __ldcs(pr + j);
#pragma unroll
    for (int j = 0; j < 4; j++) buf[1][j] = __ldcs(pr + 128 + j);

    float Bv[16];
#pragma unroll
    for (int j = 0; j < 16; j++) Bv[j] = 0.f;
    if (lane == 0) Bv[0] = 1.f;     // alpha_{-1} = delta_0

    float pc[16], Av[16], Pa[16], R[8];
    float k1, k2, k4, k8, k16;      // masked scan multipliers

    // ---- prep from a buffer slot: everything p-only ----
    auto prep = [&](const float4* bslot) {
#pragma unroll
        for (int j = 0; j < 4; j++) {
            pc[4*j+0] = bslot[j].x; pc[4*j+1] = bslot[j].y;
            pc[4*j+2] = bslot[j].z; pc[4*j+3] = bslot[j].w;
        }
        float prevlast = __shfl_up_sync(0xffffffffu, pc[15], 1);
        Av[0] = (lane == 0) ? 0.f : (1.f - prevlast);
#pragma unroll
        for (int j = 1; j < 16; j++) Av[j] = 1.f - pc[j-1];
        Pa[0] = Av[0];
#pragma unroll
        for (int j = 1; j < 8; j++) Pa[j] = Pa[j-1] * Av[j];
        R[0] = Av[8];
#pragma unroll
        for (int j = 1; j < 8; j++) R[j] = R[j-1] * Av[8+j];
#pragma unroll
        for (int j = 0; j < 8; j++) Pa[8+j] = Pa[7] * R[j];
        // cumulative cross-lane chunk products, pre-masked per scan level
        float m = Pa[15], s;
        k1  = (lane >= 1)  ? m : 0.f;
        s = __shfl_up_sync(0xffffffffu, m, 1);  m *= s;
        k2  = (lane >= 2)  ? m : 0.f;
        s = __shfl_up_sync(0xffffffffu, m, 2);  m *= s;
        k4  = (lane >= 4)  ? m : 0.f;
        s = __shfl_up_sync(0xffffffffu, m, 4);  m *= s;
        k8  = (lane >= 8)  ? m : 0.f;
        s = __shfl_up_sync(0xffffffffu, m, 8);  m *= s;
        k16 = (lane >= 16) ? m : 0.f;
    };

    prep(buf[0]);

    for (int i = 0; i < TGT; i++) {
        // prefetch row min(i+2, TGT-1) (clamped: no branch; dup loads harmless)
        {
            int pf = (i + 2 < TGT) ? (i + 2) : (TGT - 1);
            float4* bslot = buf[i & 1];
#pragma unroll
            for (int j = 0; j < 4; j++) bslot[j] = __ldcs(pr + (size_t)pf * 128 + j);
        }

        // ---- two independent half-chains of the local recurrence ----
        float Pl[8], Ph[8];
        Pl[0] = Bv[0];
#pragma unroll
        for (int j = 1; j < 8; j++) Pl[j] = fmaf(Pl[j-1], Av[j], Bv[j]);
        Ph[0] = Bv[8];
#pragma unroll
        for (int j = 1; j < 8; j++) Ph[j] = fmaf(Ph[j-1], Av[8+j], Bv[8+j]);

        // full-chunk b = low-half tail carried through high half
        float b = fmaf(Pl[7], R[7], Ph[7]);

        // ---- masked Kogge-Stone scan: unconditional fmaf per level ----
        float s;
        s = __shfl_up_sync(0xffffffffu, b, 1);  b = fmaf(s, k1,  b);
        s = __shfl_up_sync(0xffffffffu, b, 2);  b = fmaf(s, k2,  b);
        s = __shfl_up_sync(0xffffffffu, b, 4);  b = fmaf(s, k4,  b);
        s = __shfl_up_sync(0xffffffffu, b, 8);  b = fmaf(s, k8,  b);
        s = __shfl_up_sync(0xffffffffu, b, 16); b = fmaf(s, k16, b);

        float qin = __shfl_up_sync(0xffffffffu, b, 1);
        qin = (lane == 0) ? 0.f : qin;

        // ---- replay: q_j = qin*Pa[j] + Pb[j];  alpha = p*q (into Bv) ----
#pragma unroll
        for (int j = 0; j < 8; j++)
            Bv[j] = pc[j] * fmaf(qin, Pa[j], Pl[j]);
#pragma unroll
        for (int j = 0; j < 8; j++)
            Bv[8+j] = pc[8+j] * fmaf(qin, Pa[8+j], fmaf(Pl[7], R[j], Ph[j]));

        __stcs(ar + (size_t)i * 128 + 0, make_float4(Bv[0],  Bv[1],  Bv[2],  Bv[3]));
        __stcs(ar + (size_t)i * 128 + 1, make_float4(Bv[4],  Bv[5],  Bv[6],  Bv[7]));
        __stcs(ar + (size_t)i * 128 + 2, make_float4(Bv[8],  Bv[9],  Bv[10], Bv[11]));
        __stcs(ar + (size_t)i * 128 + 3, make_float4(Bv[12], Bv[13], Bv[14], Bv[15]));

        // ---- prep next step's p-only parameters (unconditional, off-chain) ----
        prep(buf[(i + 1) & 1]);
    }
}

// ---------------------------------------------------------------------------
extern "C" void kernel_launch(void* const* d_in, const int* in_sizes, int n_in,
                              void* d_out, int out_size)
{
    const float* seqs  = (const float*)d_in[0];
    const float* keys  = (const float*)d_in[1];
    const float* q_w   = (const float*)d_in[2];
    const float* q_b   = (const float*)d_in[3];
    const float* k_w   = (const float*)d_in[4];
    const float* k_b   = (const float*)d_in[5];
    const float* ebias = (const float*)d_in[6];

    float* p_out = (float*)d_out;
    float* a_out = p_out + P_ELEMS;

    void *sh, *sl, *kh, *kl, *qwh, *qwl, *kwh, *kwl;
    cudaGetSymbolAddress(&sh,  g_sh);  cudaGetSymbolAddress(&sl,  g_sl);
    cudaGetSymbolAddress(&kh,  g_kh);  cudaGetSymbolAddress(&kl,  g_kl);
    cudaGetSymbolAddress(&qwh, g_qwh); cudaGetSymbolAddress(&qwl, g_qwl);
    cudaGetSymbolAddress(&kwh, g_kwh); cudaGetSymbolAddress(&kwl, g_kwl);

    cudaFuncSetAttribute(proj_mma,   cudaFuncAttributeMaxDynamicSharedMemorySize, PROJ_SMEM);
    cudaFuncSetAttribute(energy_mma, cudaFuncAttributeMaxDynamicSharedMemorySize, E_SMEM);

    cvt_kernel<<<(MQ*D_DIM/4 + 255)/256, 256>>>((const float4*)seqs, (ushort4*)sh, (ushort4*)sl, MQ*D_DIM/4);
    cvt_kernel<<<(MK*D_DIM/4 + 255)/256, 256>>>((const float4*)keys, (ushort4*)kh, (ushort4*)kl, MK*D_DIM/4);
    cvt_kernel<<<(D_DIM*D_DIM/4 + 255)/256, 256>>>((const float4*)q_w, (ushort4*)qwh, (ushort4*)qwl, D_DIM*D_DIM/4);
    cvt_kernel<<<(D_DIM*D_DIM/4 + 255)/256, 256>>>((const float4*)k_w, (ushort4*)kwh, (ushort4*)kwl, D_DIM*D_DIM/4);

    proj_mma<<<dim3(8, 48), 256, PROJ_SMEM>>>(q_b, k_b);
    energy_mma<<<dim3(4, 2, BH), 256, E_SMEM>>>(ebias, p_out);
    alpha_kernel<<<BH, 32>>>(p_out, a_out);
}

// round 7
// speedup vs baseline: 2.4679x; 1.4689x over previous
#include <cuda_runtime.h>
#include <cuda_bf16.h>
#include <cstdint>

// ---------------------------------------------------------------------------
// B=8, TGT=256, SRC=512, D=1024, H=16, dh=64, TEMP=0.2
// Output: p_choose (8,16,256,512) then alpha (8,16,256,512), fp32.
// ---------------------------------------------------------------------------

#define D_DIM   1024
#define TGT     256
#define SRC     512
#define NB      8
#define NH      16
#define DH      64
#define BH      (NB*NH)
#define P_ELEMS ((size_t)BH*TGT*SRC)

#define MQ (NB*TGT)     // 2048
#define MK (NB*SRC)     // 4096

// bf16 hi/lo decompositions of inputs
__device__ __nv_bfloat16 g_sh[MQ*D_DIM], g_sl[MQ*D_DIM];
__device__ __nv_bfloat16 g_kh[MK*D_DIM], g_kl[MK*D_DIM];
__device__ __nv_bfloat16 g_qwh[D_DIM*D_DIM], g_qwl[D_DIM*D_DIM];
__device__ __nv_bfloat16 g_kwh[D_DIM*D_DIM], g_kwl[D_DIM*D_DIM];
// bf16 hi/lo activations (projection outputs)
__device__ __nv_bfloat16 g_aqh[MQ*D_DIM], g_aql[MQ*D_DIM];
__device__ __nv_bfloat16 g_akh[MK*D_DIM], g_akl[MK*D_DIM];

__device__ __forceinline__ void mma16816(float4& d,
    uint32_t a0, uint32_t a1, uint32_t a2, uint32_t a3,
    uint32_t b0, uint32_t b1)
{
    asm volatile(
        "mma.sync.aligned.m16n8k16.row.col.f32.bf16.bf16.f32 "
        "{%0,%1,%2,%3}, {%4,%5,%6,%7}, {%8,%9}, {%0,%1,%2,%3};"
        : "+f"(d.x), "+f"(d.y), "+f"(d.z), "+f"(d.w)
        : "r"(a0), "r"(a1), "r"(a2), "r"(a3), "r"(b0), "r"(b1));
}

__device__ __forceinline__ void cp_async16(uint32_t smem_dst, const void* gsrc) {
    asm volatile("cp.async.ca.shared.global [%0], [%1], 16;" :: "r"(smem_dst), "l"(gsrc));
}
__device__ __forceinline__ void cp_async16_cg(uint32_t smem_dst, const void* gsrc) {
    asm volatile("cp.async.cg.shared.global [%0], [%1], 16;" :: "r"(smem_dst), "l"(gsrc));
}
__device__ __forceinline__ void cp_async_commit() {
    asm volatile("cp.async.commit_group;" ::: "memory");
}
__device__ __forceinline__ void cp_async_wait0() {
    asm volatile("cp.async.wait_group 0;" ::: "memory");
}
__device__ __forceinline__ uint32_t smem_u32(const void* p) {
    uint32_t a;
    asm("{ .reg .u64 t; cvta.to.shared.u64 t, %1; cvt.u32.u64 %0, t; }" : "=r"(a) : "l"(p));
    return a;
}

// ---------------------------------------------------------------------------
// fp32 -> (hi, lo) bf16 decomposition.
// ---------------------------------------------------------------------------
__global__ __launch_bounds__(256)
void cvt_kernel(const float4* __restrict__ in, ushort4* __restrict__ hi,
                ushort4* __restrict__ lo, int n4)
{
    int i = blockIdx.x * 256 + threadIdx.x;
    if (i >= n4) return;
    float4 v = in[i];
    ushort4 h, l;
    {
        __nv_bfloat16 hb = __float2bfloat16(v.x);
        __nv_bfloat16 lb = __float2bfloat16(v.x - __bfloat162float(hb));
        h.x = *(unsigned short*)&hb; l.x = *(unsigned short*)&lb;
    }
    {
        __nv_bfloat16 hb = __float2bfloat16(v.y);
        __nv_bfloat16 lb = __float2bfloat16(v.y - __bfloat162float(hb));
        h.y = *(unsigned short*)&hb; l.y = *(unsigned short*)&lb;
    }
    {
        __nv_bfloat16 hb = __float2bfloat16(v.z);
        __nv_bfloat16 lb = __float2bfloat16(v.z - __bfloat162float(hb));
        h.z = *(unsigned short*)&hb; l.z = *(unsigned short*)&lb;
    }
    {
        __nv_bfloat16 hb = __float2bfloat16(v.w);
        __nv_bfloat16 lb = __float2bfloat16(v.w - __bfloat162float(hb));
        h.w = *(unsigned short*)&hb; l.w = *(unsigned short*)&lb;
    }
    hi[i] = h; lo[i] = l;
}

// ---------------------------------------------------------------------------
// mma.sync bf16-split projection GEMM + bias + ReLU -> bf16 hi/lo activations.
// (unchanged — known-passing)
// ---------------------------------------------------------------------------
#define CK      32
#define NCH     (D_DIM/CK)
#define STR     40
#define TILE_BYTES (128*STR*2)
#define BUF_BYTES  (4*TILE_BYTES)
#define PROJ_SMEM  (2*BUF_BYTES)

__global__ __launch_bounds__(256)
void proj_mma(const float* __restrict__ q_b, const float* __restrict__ k_b)
{
    extern __shared__ char smem[];
    const int tid  = threadIdx.x;
    const int wid  = tid >> 5;
    const int lane = tid & 31;
    const int g    = lane >> 2;
    const int t    = lane & 3;
    const int warpM = wid & 3;
    const int warpN = wid >> 2;

    const int by  = blockIdx.y;
    const bool isq = by < 16;
    const int bm  = (isq ? by : by - 16) * 128;
    const int bn  = blockIdx.x * 128;

    const __nv_bfloat16* Ah = isq ? g_sh  : g_kh;
    const __nv_bfloat16* Al = isq ? g_sl  : g_kl;
    const __nv_bfloat16* Wh = isq ? g_qwh : g_kwh;
    const __nv_bfloat16* Wl = isq ? g_qwl : g_kwl;
    const float*       bias = isq ? q_b   : k_b;
    __nv_bfloat16*       CH = isq ? g_aqh : g_akh;
    __nv_bfloat16*       CL = isq ? g_aql : g_akl;

    float4 acc[2][8];
#pragma unroll
    for (int i = 0; i < 2; i++)
#pragma unroll
        for (int j = 0; j < 8; j++) acc[i][j] = make_float4(0.f, 0.f, 0.f, 0.f);

    const uint32_t smem_base = smem_u32(smem);

    auto load_chunk = [&](int c, int buf) {
        const int k0 = c * CK;
        const uint32_t sb = smem_base + buf * BUF_BYTES;
#pragma unroll
        for (int h = 0; h < 2; h++) {
            int seg = tid + h * 256;
            int row = seg >> 2;
            int s4  = seg & 3;
            uint32_t soff = (uint32_t)(row * STR + s4 * 8) * 2;
            size_t ga = (size_t)(bm + row) * D_DIM + k0 + s4 * 8;
            size_t gw = (size_t)(bn + row) * D_DIM + k0 + s4 * 8;
            cp_async16(sb + soff,                Ah + ga);
            cp_async16(sb + TILE_BYTES   + soff, Al + ga);
            cp_async16(sb + 2*TILE_BYTES + soff, Wh + gw);
            cp_async16(sb + 3*TILE_BYTES + soff, Wl + gw);
        }
        cp_async_commit();
    };

    load_chunk(0, 0);
    cp_async_wait0();
    __syncthreads();

    for (int c = 0; c < NCH; c++) {
        const int buf = c & 1;
        if (c + 1 < NCH) load_chunk(c + 1, buf ^ 1);

        const char* tb  = smem + buf * BUF_BYTES;
        const __nv_bfloat16* sAh = (const __nv_bfloat16*)tb;
        const __nv_bfloat16* sAl = (const __nv_bfloat16*)(tb + TILE_BYTES);
        const __nv_bfloat16* sWh = (const __nv_bfloat16*)(tb + 2*TILE_BYTES);
        const __nv_bfloat16* sWl = (const __nv_bfloat16*)(tb + 3*TILE_BYTES);

#pragma unroll
        for (int ks = 0; ks < CK; ks += 16) {
            uint32_t ah[2][4], al[2][4];
#pragma unroll
            for (int i = 0; i < 2; i++) {
                int r0 = warpM * 32 + i * 16 + g;
                const __nv_bfloat16* p0 = sAh + r0 * STR + ks + 2 * t;
                const __nv_bfloat16* p1 = sAh + (r0 + 8) * STR + ks + 2 * t;
                ah[i][0] = *(const uint32_t*)p0;
                ah[i][1] = *(const uint32_t*)p1;
                ah[i][2] = *(const uint32_t*)(p0 + 8);
                ah[i][3] = *(const uint32_t*)(p1 + 8);
                const __nv_bfloat16* q0 = sAl + r0 * STR + ks + 2 * t;
                const __nv_bfloat16* q1 = sAl + (r0 + 8) * STR + ks + 2 * t;
                al[i][0] = *(const uint32_t*)q0;
                al[i][1] = *(const uint32_t*)q1;
                al[i][2] = *(const uint32_t*)(q0 + 8);
                al[i][3] = *(const uint32_t*)(q1 + 8);
            }
#pragma unroll
            for (int j = 0; j < 8; j++) {
                int rw = warpN * 64 + j * 8 + g;
                const __nv_bfloat16* pw = sWh + rw * STR + ks + 2 * t;
                uint32_t bh0 = *(const uint32_t*)pw;
                uint32_t bh1 = *(const uint32_t*)(pw + 8);
                const __nv_bfloat16* pl = sWl + rw * STR + ks + 2 * t;
                uint32_t bl0 = *(const uint32_t*)pl;
                uint32_t bl1 = *(const uint32_t*)(pl + 8);
#pragma unroll
                for (int i = 0; i < 2; i++) {
                    mma16816(acc[i][j], ah[i][0], ah[i][1], ah[i][2], ah[i][3], bh0, bh1);
                    mma16816(acc[i][j], ah[i][0], ah[i][1], ah[i][2], ah[i][3], bl0, bl1);
                    mma16816(acc[i][j], al[i][0], al[i][1], al[i][2], al[i][3], bh0, bh1);
                }
            }
        }

        cp_async_wait0();
        __syncthreads();
    }

#pragma unroll
    for (int i = 0; i < 2; i++) {
        int row0 = bm + warpM * 32 + i * 16 + g;
#pragma unroll
        for (int j = 0; j < 8; j++) {
            int col = bn + warpN * 64 + j * 8 + 2 * t;
            float b0 = bias[col], b1 = bias[col + 1];
            float v[4];
            v[0] = fmaxf(acc[i][j].x + b0, 0.f);
            v[1] = fmaxf(acc[i][j].y + b1, 0.f);
            v[2] = fmaxf(acc[i][j].z + b0, 0.f);
            v[3] = fmaxf(acc[i][j].w + b1, 0.f);
            __nv_bfloat16 h[4], l[4];
#pragma unroll
            for (int u = 0; u < 4; u++) {
                h[u] = __float2bfloat16(v[u]);
                l[u] = __float2bfloat16(v[u] - __bfloat162float(h[u]));
            }
            __nv_bfloat162 h01; h01.x = h[0]; h01.y = h[1];
            __nv_bfloat162 h23; h23.x = h[2]; h23.y = h[3];
            __nv_bfloat162 l01; l01.x = l[0]; l01.y = l[1];
            __nv_bfloat162 l23; l23.x = l[2]; l23.y = l[3];
            *(__nv_bfloat162*)(CH + (size_t)row0 * D_DIM + col)       = h01;
            *(__nv_bfloat162*)(CH + (size_t)(row0 + 8) * D_DIM + col) = h23;
            *(__nv_bfloat162*)(CL + (size_t)row0 * D_DIM + col)       = l01;
            *(__nv_bfloat162*)(CL + (size_t)(row0 + 8) * D_DIM + col) = l23;
        }
    }
}

// ---------------------------------------------------------------------------
// mma.sync bf16-split energy + sigmoid (unchanged — known-passing).
// ---------------------------------------------------------------------------
#define ESTR    72
#define ETILE_BYTES (128*ESTR*2)
#define E_SMEM  (4*ETILE_BYTES)

__global__ __launch_bounds__(256)
void energy_mma(const float* __restrict__ ebias, float* __restrict__ P)
{
    extern __shared__ char smem[];
    const int tid  = threadIdx.x;
    const int wid  = tid >> 5;
    const int lane = tid & 31;
    const int g    = lane >> 2;
    const int t    = lane & 3;
    const int warpM = wid & 3;
    const int warpN = wid >> 2;

    const int bh = blockIdx.z;
    const int bb = bh >> 4;
    const int hh = bh & 15;
    const int m0 = blockIdx.y * 128;
    const int n0 = blockIdx.x * 128;

    const __nv_bfloat16* Qh = g_aqh + (size_t)bb * TGT * D_DIM + hh * DH;
    const __nv_bfloat16* Ql = g_aql + (size_t)bb * TGT * D_DIM + hh * DH;
    const __nv_bfloat16* Kh = g_akh + (size_t)bb * SRC * D_DIM + hh * DH;
    const __nv_bfloat16* Kl = g_akl + (size_t)bb * SRC * D_DIM + hh * DH;

    const uint32_t sb = smem_u32(smem);

#pragma unroll
    for (int h = 0; h < 4; h++) {
        int seg = tid + h * 256;
        int row = seg >> 3;
        int s   = seg & 7;
        uint32_t soff = (uint32_t)(row * ESTR + s * 8) * 2;
        cp_async16(sb + soff,                 Qh + (size_t)(m0 + row) * D_DIM + s * 8);
        cp_async16(sb + ETILE_BYTES   + soff, Ql + (size_t)(m0 + row) * D_DIM + s * 8);
        cp_async16(sb + 2*ETILE_BYTES + soff, Kh + (size_t)(n0 + row) * D_DIM + s * 8);
        cp_async16(sb + 3*ETILE_BYTES + soff, Kl + (size_t)(n0 + row) * D_DIM + s * 8);
    }
    cp_async_commit();
    cp_async_wait0();
    __syncthreads();

    const __nv_bfloat16* sQh = (const __nv_bfloat16*)smem;
    const __nv_bfloat16* sQl = (const __nv_bfloat16*)(smem + ETILE_BYTES);
    const __nv_bfloat16* sKh = (const __nv_bfloat16*)(smem + 2*ETILE_BYTES);
    const __nv_bfloat16* sKl = (const __nv_bfloat16*)(smem + 3*ETILE_BYTES);

    float4 acc[2][8];
#pragma unroll
    for (int i = 0; i < 2; i++)
#pragma unroll
        for (int j = 0; j < 8; j++) acc[i][j] = make_float4(0.f, 0.f, 0.f, 0.f);

#pragma unroll
    for (int ks = 0; ks < DH; ks += 16) {
        uint32_t ah[2][4], al[2][4];
#pragma unroll
        for (int i = 0; i < 2; i++) {
            int r0 = warpM * 32 + i * 16 + g;
            const __nv_bfloat16* p0 = sQh + r0 * ESTR + ks + 2 * t;
            const __nv_bfloat16* p1 = sQh + (r0 + 8) * ESTR + ks + 2 * t;
            ah[i][0] = *(const uint32_t*)p0;
            ah[i][1] = *(const uint32_t*)p1;
            ah[i][2] = *(const uint32_t*)(p0 + 8);
            ah[i][3] = *(const uint32_t*)(p1 + 8);
            const __nv_bfloat16* q0 = sQl + r0 * ESTR + ks + 2 * t;
            const __nv_bfloat16* q1 = sQl + (r0 + 8) * ESTR + ks + 2 * t;
            al[i][0] = *(const uint32_t*)q0;
            al[i][1] = *(const uint32_t*)q1;
            al[i][2] = *(const uint32_t*)(q0 + 8);
            al[i][3] = *(const uint32_t*)(q1 + 8);
        }
#pragma unroll
        for (int j = 0; j < 8; j++) {
            int rw = warpN * 64 + j * 8 + g;
            const __nv_bfloat16* pw = sKh + rw * ESTR + ks + 2 * t;
            uint32_t bh0 = *(const uint32_t*)pw;
            uint32_t bh1 = *(const uint32_t*)(pw + 8);
            const __nv_bfloat16* pl = sKl + rw * ESTR + ks + 2 * t;
            uint32_t bl0 = *(const uint32_t*)pl;
            uint32_t bl1 = *(const uint32_t*)(pl + 8);
#pragma unroll
            for (int i = 0; i < 2; i++) {
                mma16816(acc[i][j], ah[i][0], ah[i][1], ah[i][2], ah[i][3], bh0, bh1);
                mma16816(acc[i][j], ah[i][0], ah[i][1], ah[i][2], ah[i][3], bl0, bl1);
                mma16816(acc[i][j], al[i][0], al[i][1], al[i][2], al[i][3], bh0, bh1);
            }
        }
    }

    const float eb5 = ebias[0] * 5.0f;

#pragma unroll
    for (int i = 0; i < 2; i++) {
        int row0 = m0 + warpM * 32 + i * 16 + g;
#pragma unroll
        for (int j = 0; j < 8; j++) {
            int col = n0 + warpN * 64 + j * 8 + 2 * t;
            float z0 = fmaf(acc[i][j].x, 0.625f, eb5);
            float z1 = fmaf(acc[i][j].y, 0.625f, eb5);
            float z2 = fmaf(acc[i][j].z, 0.625f, eb5);
            float z3 = fmaf(acc[i][j].w, 0.625f, eb5);
            float2 o0, o1;
            o0.x = 1.0f / (1.0f + __expf(-z0));
            o0.y = 1.0f / (1.0f + __expf(-z1));
            o1.x = 1.0f / (1.0f + __expf(-z2));
            o1.y = 1.0f / (1.0f + __expf(-z3));
            float* dst0 = P + ((size_t)bh * TGT + row0) * SRC + col;
            float* dst1 = P + ((size_t)bh * TGT + row0 + 8) * SRC + col;
            *(float2*)dst0 = o0;
            *(float2*)dst1 = o1;
        }
    }
}

// ---------------------------------------------------------------------------
// Monotonic alignment v4: cp.async smem ring (depth 8) + register diet.
//   q[n] = q[n-1]*A[n] + B[n],  A[n]=1-p_i[n-1] (A[0]=0), B[n]=alpha_{i-1}[n]
//   alpha_i[n] = p_i[n]*q[n]
// Per step: recompute Av from pc (parallel), two 8-long half-chains,
// masked Kogge-Stone scan with precomputed multipliers, independent replay.
// Lane l's p data staged at smem (c*32+l)*16 -> conflict-free LDS.128 and
// lane-local (no sync needed; wait_group orders own cp.asyncs).
// ---------------------------------------------------------------------------
__global__ __launch_bounds__(32)
void alpha_kernel(const float* __restrict__ p, float* __restrict__ alpha)
{
    __shared__ float4 srow[8 * 128];          // 8 slots x 2048B ring
    const int lane = threadIdx.x;
    const int bh   = blockIdx.x;

    const float* pg = p + (size_t)bh * TGT * SRC;
    float4*      ar = (float4*)(alpha + (size_t)bh * TGT * SRC + lane * 16);
    const uint32_t sbase = smem_u32(srow);

    auto issue_row = [&](int r) {
        int rc = (r < TGT) ? r : (TGT - 1);
        uint32_t slot = (uint32_t)(r & 7);
        const float* src = pg + (size_t)rc * SRC + lane * 16;
#pragma unroll
        for (int c = 0; c < 4; c++)
            cp_async16_cg(sbase + slot * 2048 + (uint32_t)(c * 32 + lane) * 16,
                          src + c * 4);
        cp_async_commit();
    };

    // prologue: rows 0..6 in flight; wait so row 0 is resident
#pragma unroll
    for (int r = 0; r < 7; r++) issue_row(r);
    asm volatile("cp.async.wait_group 6;" ::: "memory");

    float Bv[16];
#pragma unroll
    for (int j = 0; j < 16; j++) Bv[j] = 0.f;
    if (lane == 0) Bv[0] = 1.f;               // alpha_{-1} = delta_0

    float pc[16], PaL[8], PaH[8];
    float Av0;                                 // carried A[0] for current row
    float k1, k2, k4, k8, k16;                 // masked scan multipliers

    // p-only prep for a row resident in the ring
    auto prep = [&](int row) {
        uint32_t slot = (uint32_t)(row & 7);
        const float4* base = srow + slot * 128 + lane;
        float4 f0 = base[0];
        float4 f1 = base[32];
        float4 f2 = base[64];
        float4 f3 = base[96];
        pc[0]=f0.x;  pc[1]=f0.y;  pc[2]=f0.z;  pc[3]=f0.w;
        pc[4]=f1.x;  pc[5]=f1.y;  pc[6]=f1.z;  pc[7]=f1.w;
        pc[8]=f2.x;  pc[9]=f2.y;  pc[10]=f2.z; pc[11]=f2.w;
        pc[12]=f3.x; pc[13]=f3.y; pc[14]=f3.z; pc[15]=f3.w;
        float prevlast = __shfl_up_sync(0xffffffffu, pc[15], 1);
        Av0 = (lane == 0) ? 0.f : (1.f - prevlast);
        float Av[16];
        Av[0] = Av0;
#pragma unroll
        for (int j = 1; j < 16; j++) Av[j] = 1.f - pc[j-1];
        PaL[0] = Av[0];
#pragma unroll
        for (int j = 1; j < 8; j++) PaL[j] = PaL[j-1] * Av[j];
        PaH[0] = Av[8];
#pragma unroll
        for (int j = 1; j < 8; j++) PaH[j] = PaH[j-1] * Av[8+j];
        float m = PaL[7] * PaH[7], s;
        k1  = (lane >= 1)  ? m : 0.f;
        s = __shfl_up_sync(0xffffffffu, m, 1);  m *= s;
        k2  = (lane >= 2)  ? m : 0.f;
        s = __shfl_up_sync(0xffffffffu, m, 2);  m *= s;
        k4  = (lane >= 4)  ? m : 0.f;
        s = __shfl_up_sync(0xffffffffu, m, 4);  m *= s;
        k8  = (lane >= 8)  ? m : 0.f;
        s = __shfl_up_sync(0xffffffffu, m, 8);  m *= s;
        k16 = (lane >= 16) ? m : 0.f;
    };

    prep(0);

    for (int i = 0; i < TGT; i++) {
        // keep the ring full: row i+7 in, then guarantee row i+1 resident
        issue_row(i + 7);
        asm volatile("cp.async.wait_group 6;" ::: "memory");

        // recompute Av (parallel FADDs, feeds half-chains)
        float Av[16];
        Av[0] = Av0;
#pragma unroll
        for (int j = 1; j < 16; j++) Av[j] = 1.f - pc[j-1];

        // two independent 8-long half-chains
        float Pl[8], Ph[8];
        Pl[0] = Bv[0];
#pragma unroll
        for (int j = 1; j < 8; j++) Pl[j] = fmaf(Pl[j-1], Av[j], Bv[j]);
        Ph[0] = Bv[8];
#pragma unroll
        for (int j = 1; j < 8; j++) Ph[j] = fmaf(Ph[j-1], Av[8+j], Bv[8+j]);

        float b = fmaf(Pl[7], PaH[7], Ph[7]);

        // masked Kogge-Stone scan: unconditional fmaf per level
        float s;
        s = __shfl_up_sync(0xffffffffu, b, 1);  b = fmaf(s, k1,  b);
        s = __shfl_up_sync(0xffffffffu, b, 2);  b = fmaf(s, k2,  b);
        s = __shfl_up_sync(0xffffffffu, b, 4);  b = fmaf(s, k4,  b);
        s = __shfl_up_sync(0xffffffffu, b, 8);  b = fmaf(s, k8,  b);
        s = __shfl_up_sync(0xffffffffu, b, 16); b = fmaf(s, k16, b);

        float qin = __shfl_up_sync(0xffffffffu, b, 1);
        qin = (lane == 0) ? 0.f : qin;
        float qmid = fmaf(qin, PaL[7], Pl[7]);   // q after element 7

        // replay: independent fmas; alpha into Bv
#pragma unroll
        for (int j = 0; j < 8; j++)
            Bv[j] = pc[j] * fmaf(qin, PaL[j], Pl[j]);
#pragma unroll
        for (int j = 0; j < 8; j++)
            Bv[8+j] = pc[8+j] * fmaf(qmid, PaH[j], Ph[j]);

        __stcs(ar + (size_t)i * 128 + 0, make_float4(Bv[0],  Bv[1],  Bv[2],  Bv[3]));
        __stcs(ar + (size_t)i * 128 + 1, make_float4(Bv[4],  Bv[5],  Bv[6],  Bv[7]));
        __stcs(ar + (size_t)i * 128 + 2, make_float4(Bv[8],  Bv[9],  Bv[10], Bv[11]));
        __stcs(ar + (size_t)i * 128 + 3, make_float4(Bv[12], Bv[13], Bv[14], Bv[15]));

        // prep next row's p-only parameters (off the alpha-dependence chain)
        prep(i + 1);
    }
}

// ---------------------------------------------------------------------------
extern "C" void kernel_launch(void* const* d_in, const int* in_sizes, int n_in,
                              void* d_out, int out_size)
{
    const float* seqs  = (const float*)d_in[0];
    const float* keys  = (const float*)d_in[1];
    const float* q_w   = (const float*)d_in[2];
    const float* q_b   = (const float*)d_in[3];
    const float* k_w   = (const float*)d_in[4];
    const float* k_b   = (const float*)d_in[5];
    const float* ebias = (const float*)d_in[6];

    float* p_out = (float*)d_out;
    float* a_out = p_out + P_ELEMS;

    void *sh, *sl, *kh, *kl, *qwh, *qwl, *kwh, *kwl;
    cudaGetSymbolAddress(&sh,  g_sh);  cudaGetSymbolAddress(&sl,  g_sl);
    cudaGetSymbolAddress(&kh,  g_kh);  cudaGetSymbolAddress(&kl,  g_kl);
    cudaGetSymbolAddress(&qwh, g_qwh); cudaGetSymbolAddress(&qwl, g_qwl);
    cudaGetSymbolAddress(&kwh, g_kwh); cudaGetSymbolAddress(&kwl, g_kwl);

    cudaFuncSetAttribute(proj_mma,   cudaFuncAttributeMaxDynamicSharedMemorySize, PROJ_SMEM);
    cudaFuncSetAttribute(energy_mma, cudaFuncAttributeMaxDynamicSharedMemorySize, E_SMEM);

    cvt_kernel<<<(MQ*D_DIM/4 + 255)/256, 256>>>((const float4*)seqs, (ushort4*)sh, (ushort4*)sl, MQ*D_DIM/4);
    cvt_kernel<<<(MK*D_DIM/4 + 255)/256, 256>>>((const float4*)keys, (ushort4*)kh, (ushort4*)kl, MK*D_DIM/4);
    cvt_kernel<<<(D_DIM*D_DIM/4 + 255)/256, 256>>>((const float4*)q_w, (ushort4*)qwh, (ushort4*)qwl, D_DIM*D_DIM/4);
    cvt_kernel<<<(D_DIM*D_DIM/4 + 255)/256, 256>>>((const float4*)k_w, (ushort4*)kwh, (ushort4*)kwl, D_DIM*D_DIM/4);

    proj_mma<<<dim3(8, 48), 256, PROJ_SMEM>>>(q_b, k_b);
    energy_mma<<<dim3(4, 2, BH), 256, E_SMEM>>>(ebias, p_out);
    alpha_kernel<<<BH, 32>>>(p_out, a_out);
}

// round 8
// speedup vs baseline: 2.7908x; 1.1308x over previous
#include <cuda_runtime.h>
#include <cuda_bf16.h>
#include <cstdint>

// ---------------------------------------------------------------------------
// B=8, TGT=256, SRC=512, D=1024, H=16, dh=64, TEMP=0.2
// Output: p_choose (8,16,256,512) then alpha (8,16,256,512), fp32.
// ---------------------------------------------------------------------------

#define D_DIM   1024
#define TGT     256
#define SRC     512
#define NB      8
#define NH      16
#define DH      64
#define BH      (NB*NH)
#define P_ELEMS ((size_t)BH*TGT*SRC)

#define MQ (NB*TGT)     // 2048
#define MK (NB*SRC)     // 4096

// bf16 hi/lo decompositions of inputs
__device__ __nv_bfloat16 g_sh[MQ*D_DIM], g_sl[MQ*D_DIM];
__device__ __nv_bfloat16 g_kh[MK*D_DIM], g_kl[MK*D_DIM];
__device__ __nv_bfloat16 g_qwh[D_DIM*D_DIM], g_qwl[D_DIM*D_DIM];
__device__ __nv_bfloat16 g_kwh[D_DIM*D_DIM], g_kwl[D_DIM*D_DIM];
// bf16 hi/lo activations (projection outputs)
__device__ __nv_bfloat16 g_aqh[MQ*D_DIM], g_aql[MQ*D_DIM];
__device__ __nv_bfloat16 g_akh[MK*D_DIM], g_akl[MK*D_DIM];

__device__ __forceinline__ void mma16816(float4& d,
    uint32_t a0, uint32_t a1, uint32_t a2, uint32_t a3,
    uint32_t b0, uint32_t b1)
{
    asm volatile(
        "mma.sync.aligned.m16n8k16.row.col.f32.bf16.bf16.f32 "
        "{%0,%1,%2,%3}, {%4,%5,%6,%7}, {%8,%9}, {%0,%1,%2,%3};"
        : "+f"(d.x), "+f"(d.y), "+f"(d.z), "+f"(d.w)
        : "r"(a0), "r"(a1), "r"(a2), "r"(a3), "r"(b0), "r"(b1));
}

__device__ __forceinline__ void ldm_x4(uint32_t& r0, uint32_t& r1,
                                       uint32_t& r2, uint32_t& r3, uint32_t addr)
{
    asm volatile("ldmatrix.sync.aligned.m8n8.x4.shared.b16 {%0,%1,%2,%3}, [%4];"
                 : "=r"(r0), "=r"(r1), "=r"(r2), "=r"(r3) : "r"(addr));
}

__device__ __forceinline__ void cp_async16(uint32_t smem_dst, const void* gsrc) {
    asm volatile("cp.async.ca.shared.global [%0], [%1], 16;" :: "r"(smem_dst), "l"(gsrc));
}
__device__ __forceinline__ void cp_async16_cg(uint32_t smem_dst, const void* gsrc) {
    asm volatile("cp.async.cg.shared.global [%0], [%1], 16;" :: "r"(smem_dst), "l"(gsrc));
}
__device__ __forceinline__ void cp_async_commit() {
    asm volatile("cp.async.commit_group;" ::: "memory");
}
__device__ __forceinline__ void cp_async_wait0() {
    asm volatile("cp.async.wait_group 0;" ::: "memory");
}
__device__ __forceinline__ uint32_t smem_u32(const void* p) {
    uint32_t a;
    asm("{ .reg .u64 t; cvta.to.shared.u64 t, %1; cvt.u32.u64 %0, t; }" : "=r"(a) : "l"(p));
    return a;
}

// ---------------------------------------------------------------------------
// Fused fp32 -> (hi, lo) bf16 decomposition for all 4 inputs (one launch).
// Region layout (in float4 units): seqs 524288 | keys 1048576 | q_w 262144 | k_w 262144
// ---------------------------------------------------------------------------
#define N4_S  (MQ*D_DIM/4)           // 524288  -> 2048 blocks
#define N4_K  (MK*D_DIM/4)           // 1048576 -> 4096 blocks
#define N4_W  (D_DIM*D_DIM/4)        // 262144  -> 1024 blocks
#define CVT_BLOCKS ((N4_S + N4_K + 2*N4_W)/256)

__global__ __launch_bounds__(256)
void cvt_all(const float4* __restrict__ s,  const float4* __restrict__ k,
             const float4* __restrict__ qw, const float4* __restrict__ kw,
             ushort4* __restrict__ sh,  ushort4* __restrict__ sl,
             ushort4* __restrict__ kh,  ushort4* __restrict__ kl,
             ushort4* __restrict__ qwh, ushort4* __restrict__ qwl,
             ushort4* __restrict__ kwh, ushort4* __restrict__ kwl)
{
    int b = blockIdx.x;
    const float4* in; ushort4 *hi, *lo; int idx;
    if (b < N4_S/256) {
        in = s; hi = sh; lo = sl; idx = b * 256 + threadIdx.x;
    } else if (b < (N4_S + N4_K)/256) {
        in = k; hi = kh; lo = kl; idx = (b - N4_S/256) * 256 + threadIdx.x;
    } else if (b < (N4_S + N4_K + N4_W)/256) {
        in = qw; hi = qwh; lo = qwl; idx = (b - (N4_S + N4_K)/256) * 256 + threadIdx.x;
    } else {
        in = kw; hi = kwh; lo = kwl; idx = (b - (N4_S + N4_K + N4_W)/256) * 256 + threadIdx.x;
    }
    float4 v = in[idx];
    ushort4 h, l;
    {
        __nv_bfloat16 hb = __float2bfloat16(v.x);
        __nv_bfloat16 lb = __float2bfloat16(v.x - __bfloat162float(hb));
        h.x = *(unsigned short*)&hb; l.x = *(unsigned short*)&lb;
    }
    {
        __nv_bfloat16 hb = __float2bfloat16(v.y);
        __nv_bfloat16 lb = __float2bfloat16(v.y - __bfloat162float(hb));
        h.y = *(unsigned short*)&hb; l.y = *(unsigned short*)&lb;
    }
    {
        __nv_bfloat16 hb = __float2bfloat16(v.z);
        __nv_bfloat16 lb = __float2bfloat16(v.z - __bfloat162float(hb));
        h.z = *(unsigned short*)&hb; l.z = *(unsigned short*)&lb;
    }
    {
        __nv_bfloat16 hb = __float2bfloat16(v.w);
        __nv_bfloat16 lb = __float2bfloat16(v.w - __bfloat162float(hb));
        h.w = *(unsigned short*)&hb; l.w = *(unsigned short*)&lb;
    }
    hi[idx] = h; lo[idx] = l;
}

// ---------------------------------------------------------------------------
// mma.sync bf16-split projection GEMM + bias + ReLU -> bf16 hi/lo activations.
// CTA tile 128x128, 8 warps (4M x 2N), warp tile 32x64. K chunk 32, cp.async x2.
// Fragments via ldmatrix.x4 (12 per k-step instead of 48 scalar LDS).
// ---------------------------------------------------------------------------
#define CK      32
#define NCH     (D_DIM/CK)
#define STR     40
#define TILE_BYTES (128*STR*2)
#define BUF_BYTES  (4*TILE_BYTES)
#define PROJ_SMEM  (2*BUF_BYTES)

__global__ __launch_bounds__(256)
void proj_mma(const float* __restrict__ q_b, const float* __restrict__ k_b)
{
    extern __shared__ char smem[];
    const int tid  = threadIdx.x;
    const int wid  = tid >> 5;
    const int lane = tid & 31;
    const int g    = lane >> 2;
    const int t    = lane & 3;
    const int warpM = wid & 3;
    const int warpN = wid >> 2;

    const int by  = blockIdx.y;
    const bool isq = by < 16;
    const int bm  = (isq ? by : by - 16) * 128;
    const int bn  = blockIdx.x * 128;

    const __nv_bfloat16* Ah = isq ? g_sh  : g_kh;
    const __nv_bfloat16* Al = isq ? g_sl  : g_kl;
    const __nv_bfloat16* Wh = isq ? g_qwh : g_kwh;
    const __nv_bfloat16* Wl = isq ? g_qwl : g_kwl;
    const float*       bias = isq ? q_b   : k_b;
    __nv_bfloat16*       CH = isq ? g_aqh : g_akh;
    __nv_bfloat16*       CL = isq ? g_aql : g_akl;

    float4 acc[2][8];
#pragma unroll
    for (int i = 0; i < 2; i++)
#pragma unroll
        for (int j = 0; j < 8; j++) acc[i][j] = make_float4(0.f, 0.f, 0.f, 0.f);

    const uint32_t smem_base = smem_u32(smem);

    // ldmatrix per-lane address components (element units within a tile)
    const int aRow    = lane & 15;                               // m within 16
    const int aColOff = (lane >> 4) * 8;                         // 0 or 8 (k)
    const int wRowOff = (lane & 7) + ((lane >> 4) & 1) * 8;      // n within 16
    const int wColOff = ((lane >> 3) & 1) * 8;                   // 0 or 8 (k)

    auto load_chunk = [&](int c, int buf) {
        const int k0 = c * CK;
        const uint32_t sb = smem_base + buf * BUF_BYTES;
#pragma unroll
        for (int h = 0; h < 2; h++) {
            int seg = tid + h * 256;
            int row = seg >> 2;
            int s4  = seg & 3;
            uint32_t soff = (uint32_t)(row * STR + s4 * 8) * 2;
            size_t ga = (size_t)(bm + row) * D_DIM + k0 + s4 * 8;
            size_t gw = (size_t)(bn + row) * D_DIM + k0 + s4 * 8;
            cp_async16(sb + soff,                Ah + ga);
            cp_async16(sb + TILE_BYTES   + soff, Al + ga);
            cp_async16(sb + 2*TILE_BYTES + soff, Wh + gw);
            cp_async16(sb + 3*TILE_BYTES + soff, Wl + gw);
        }
        cp_async_commit();
    };

    load_chunk(0, 0);
    cp_async_wait0();
    __syncthreads();

    for (int c = 0; c < NCH; c++) {
        const int buf = c & 1;
        if (c + 1 < NCH) load_chunk(c + 1, buf ^ 1);

        const uint32_t sbAh = smem_base + buf * BUF_BYTES;
        const uint32_t sbAl = sbAh + TILE_BYTES;
        const uint32_t sbWh = sbAh + 2*TILE_BYTES;
        const uint32_t sbWl = sbAh + 3*TILE_BYTES;

        // per-thread ldmatrix base addresses (bytes)
        uint32_t aH0 = sbAh + (uint32_t)((warpM*32 +      aRow) * STR + aColOff) * 2;
        uint32_t aH1 = sbAh + (uint32_t)((warpM*32 + 16 + aRow) * STR + aColOff) * 2;
        uint32_t aL0 = sbAl + (uint32_t)((warpM*32 +      aRow) * STR + aColOff) * 2;
        uint32_t aL1 = sbAl + (uint32_t)((warpM*32 + 16 + aRow) * STR + aColOff) * 2;
        uint32_t wH  = sbWh + (uint32_t)((warpN*64 + wRowOff) * STR + wColOff) * 2;
        uint32_t wL  = sbWl + (uint32_t)((warpN*64 + wRowOff) * STR + wColOff) * 2;

#pragma unroll
        for (int ks = 0; ks < CK; ks += 16) {
            const uint32_t kso = (uint32_t)ks * 2;
            uint32_t ah[2][4], al[2][4];
            ldm_x4(ah[0][0], ah[0][1], ah[0][2], ah[0][3], aH0 + kso);
            ldm_x4(ah[1][0], ah[1][1], ah[1][2], ah[1][3], aH1 + kso);
            ldm_x4(al[0][0], al[0][1], al[0][2], al[0][3], aL0 + kso);
            ldm_x4(al[1][0], al[1][1], al[1][2], al[1][3], aL1 + kso);
#pragma unroll
            for (int jj = 0; jj < 8; jj += 2) {
                const uint32_t joff = (uint32_t)(jj * 8 * STR) * 2;
                uint32_t bh0a, bh1a, bh0b, bh1b;
                ldm_x4(bh0a, bh1a, bh0b, bh1b, wH + joff + kso);
                uint32_t bl0a, bl1a, bl0b, bl1b;
                ldm_x4(bl0a, bl1a, bl0b, bl1b, wL + joff + kso);
#pragma unroll
                for (int i = 0; i < 2; i++) {
                    mma16816(acc[i][jj],   ah[i][0], ah[i][1], ah[i][2], ah[i][3], bh0a, bh1a);
                    mma16816(acc[i][jj],   ah[i][0], ah[i][1], ah[i][2], ah[i][3], bl0a, bl1a);
                    mma16816(acc[i][jj],   al[i][0], al[i][1], al[i][2], al[i][3], bh0a, bh1a);
                    mma16816(acc[i][jj+1], ah[i][0], ah[i][1], ah[i][2], ah[i][3], bh0b, bh1b);
                    mma16816(acc[i][jj+1], ah[i][0], ah[i][1], ah[i][2], ah[i][3], bl0b, bl1b);
                    mma16816(acc[i][jj+1], al[i][0], al[i][1], al[i][2], al[i][3], bh0b, bh1b);
                }
            }
        }

        cp_async_wait0();
        __syncthreads();
    }

#pragma unroll
    for (int i = 0; i < 2; i++) {
        int row0 = bm + warpM * 32 + i * 16 + g;
#pragma unroll
        for (int j = 0; j < 8; j++) {
            int col = bn + warpN * 64 + j * 8 + 2 * t;
            float b0 = bias[col], b1 = bias[col + 1];
            float v[4];
            v[0] = fmaxf(acc[i][j].x + b0, 0.f);
            v[1] = fmaxf(acc[i][j].y + b1, 0.f);
            v[2] = fmaxf(acc[i][j].z + b0, 0.f);
            v[3] = fmaxf(acc[i][j].w + b1, 0.f);
            __nv_bfloat16 h[4], l[4];
#pragma unroll
            for (int u = 0; u < 4; u++) {
                h[u] = __float2bfloat16(v[u]);
                l[u] = __float2bfloat16(v[u] - __bfloat162float(h[u]));
            }
            __nv_bfloat162 h01; h01.x = h[0]; h01.y = h[1];
            __nv_bfloat162 h23; h23.x = h[2]; h23.y = h[3];
            __nv_bfloat162 l01; l01.x = l[0]; l01.y = l[1];
            __nv_bfloat162 l23; l23.x = l[2]; l23.y = l[3];
            *(__nv_bfloat162*)(CH + (size_t)row0 * D_DIM + col)       = h01;
            *(__nv_bfloat162*)(CH + (size_t)(row0 + 8) * D_DIM + col) = h23;
            *(__nv_bfloat162*)(CL + (size_t)row0 * D_DIM + col)       = l01;
            *(__nv_bfloat162*)(CL + (size_t)(row0 + 8) * D_DIM + col) = l23;
        }
    }
}

// ---------------------------------------------------------------------------
// mma.sync bf16-split energy + sigmoid (unchanged — known-passing).
// ---------------------------------------------------------------------------
#define ESTR    72
#define ETILE_BYTES (128*ESTR*2)
#define E_SMEM  (4*ETILE_BYTES)

__global__ __launch_bounds__(256)
void energy_mma(const float* __restrict__ ebias, float* __restrict__ P)
{
    extern __shared__ char smem[];
    const int tid  = threadIdx.x;
    const int wid  = tid >> 5;
    const int lane = tid & 31;
    const int g    = lane >> 2;
    const int t    = lane & 3;
    const int warpM = wid & 3;
    const int warpN = wid >> 2;

    const int bh = blockIdx.z;
    const int bb = bh >> 4;
    const int hh = bh & 15;
    const int m0 = blockIdx.y * 128;
    const int n0 = blockIdx.x * 128;

    const __nv_bfloat16* Qh = g_aqh + (size_t)bb * TGT * D_DIM + hh * DH;
    const __nv_bfloat16* Ql = g_aql + (size_t)bb * TGT * D_DIM + hh * DH;
    const __nv_bfloat16* Kh = g_akh + (size_t)bb * SRC * D_DIM + hh * DH;
    const __nv_bfloat16* Kl = g_akl + (size_t)bb * SRC * D_DIM + hh * DH;

    const uint32_t sb = smem_u32(smem);

#pragma unroll
    for (int h = 0; h < 4; h++) {
        int seg = tid + h * 256;
        int row = seg >> 3;
        int s   = seg & 7;
        uint32_t soff = (uint32_t)(row * ESTR + s * 8) * 2;
        cp_async16(sb + soff,                 Qh + (size_t)(m0 + row) * D_DIM + s * 8);
        cp_async16(sb + ETILE_BYTES   + soff, Ql + (size_t)(m0 + row) * D_DIM + s * 8);
        cp_async16(sb + 2*ETILE_BYTES + soff, Kh + (size_t)(n0 + row) * D_DIM + s * 8);
        cp_async16(sb + 3*ETILE_BYTES + soff, Kl + (size_t)(n0 + row) * D_DIM + s * 8);
    }
    cp_async_commit();
    cp_async_wait0();
    __syncthreads();

    const __nv_bfloat16* sQh = (const __nv_bfloat16*)smem;
    const __nv_bfloat16* sQl = (const __nv_bfloat16*)(smem + ETILE_BYTES);
    const __nv_bfloat16* sKh = (const __nv_bfloat16*)(smem + 2*ETILE_BYTES);
    const __nv_bfloat16* sKl = (const __nv_bfloat16*)(smem + 3*ETILE_BYTES);

    float4 acc[2][8];
#pragma unroll
    for (int i = 0; i < 2; i++)
#pragma unroll
        for (int j = 0; j < 8; j++) acc[i][j] = make_float4(0.f, 0.f, 0.f, 0.f);

#pragma unroll
    for (int ks = 0; ks < DH; ks += 16) {
        uint32_t ah[2][4], al[2][4];
#pragma unroll
        for (int i = 0; i < 2; i++) {
            int r0 = warpM * 32 + i * 16 + g;
            const __nv_bfloat16* p0 = sQh + r0 * ESTR + ks + 2 * t;
            const __nv_bfloat16* p1 = sQh + (r0 + 8) * ESTR + ks + 2 * t;
            ah[i][0] = *(const uint32_t*)p0;
            ah[i][1] = *(const uint32_t*)p1;
            ah[i][2] = *(const uint32_t*)(p0 + 8);
            ah[i][3] = *(const uint32_t*)(p1 + 8);
            const __nv_bfloat16* q0 = sQl + r0 * ESTR + ks + 2 * t;
            const __nv_bfloat16* q1 = sQl + (r0 + 8) * ESTR + ks + 2 * t;
            al[i][0] = *(const uint32_t*)q0;
            al[i][1] = *(const uint32_t*)q1;
            al[i][2] = *(const uint32_t*)(q0 + 8);
            al[i][3] = *(const uint32_t*)(q1 + 8);
        }
#pragma unroll
        for (int j = 0; j < 8; j++) {
            int rw = warpN * 64 + j * 8 + g;
            const __nv_bfloat16* pw = sKh + rw * ESTR + ks + 2 * t;
            uint32_t bh0 = *(const uint32_t*)pw;
            uint32_t bh1 = *(const uint32_t*)(pw + 8);
            const __nv_bfloat16* pl = sKl + rw * ESTR + ks + 2 * t;
            uint32_t bl0 = *(const uint32_t*)pl;
            uint32_t bl1 = *(const uint32_t*)(pl + 8);
#pragma unroll
            for (int i = 0; i < 2; i++) {
                mma16816(acc[i][j], ah[i][0], ah[i][1], ah[i][2], ah[i][3], bh0, bh1);
                mma16816(acc[i][j], ah[i][0], ah[i][1], ah[i][2], ah[i][3], bl0, bl1);
                mma16816(acc[i][j], al[i][0], al[i][1], al[i][2], al[i][3], bh0, bh1);
            }
        }
    }

    const float eb5 = ebias[0] * 5.0f;

#pragma unroll
    for (int i = 0; i < 2; i++) {
        int row0 = m0 + warpM * 32 + i * 16 + g;
#pragma unroll
        for (int j = 0; j < 8; j++) {
            int col = n0 + warpN * 64 + j * 8 + 2 * t;
            float z0 = fmaf(acc[i][j].x, 0.625f, eb5);
            float z1 = fmaf(acc[i][j].y, 0.625f, eb5);
            float z2 = fmaf(acc[i][j].z, 0.625f, eb5);
            float z3 = fmaf(acc[i][j].w, 0.625f, eb5);
            float2 o0, o1;
            o0.x = 1.0f / (1.0f + __expf(-z0));
            o0.y = 1.0f / (1.0f + __expf(-z1));
            o1.x = 1.0f / (1.0f + __expf(-z2));
            o1.y = 1.0f / (1.0f + __expf(-z3));
            float* dst0 = P + ((size_t)bh * TGT + row0) * SRC + col;
            float* dst1 = P + ((size_t)bh * TGT + row0 + 8) * SRC + col;
            *(float2*)dst0 = o0;
            *(float2*)dst1 = o1;
        }
    }
}

// ---------------------------------------------------------------------------
// Monotonic alignment v5: v4 + software-pipelined LDS (next-row smem reads
// hoisted to the top of the iteration; prep consumes registers at the bottom).
// ---------------------------------------------------------------------------
__global__ __launch_bounds__(32)
void alpha_kernel(const float* __restrict__ p, float* __restrict__ alpha)
{
    __shared__ float4 srow[8 * 128];          // 8 slots x 2048B ring
    const int lane = threadIdx.x;
    const int bh   = blockIdx.x;

    const float* pg = p + (size_t)bh * TGT * SRC;
    float4*      ar = (float4*)(alpha + (size_t)bh * TGT * SRC + lane * 16);
    const uint32_t sbase = smem_u32(srow);

    auto issue_row = [&](int r) {
        int rc = (r < TGT) ? r : (TGT - 1);
        uint32_t slot = (uint32_t)(r & 7);
        const float* src = pg + (size_t)rc * SRC + lane * 16;
#pragma unroll
        for (int c = 0; c < 4; c++)
            cp_async16_cg(sbase + slot * 2048 + (uint32_t)(c * 32 + lane) * 16,
                          src + c * 4);
        cp_async_commit();
    };

#pragma unroll
    for (int r = 0; r < 7; r++) issue_row(r);
    asm volatile("cp.async.wait_group 6;" ::: "memory");

    float Bv[16];
#pragma unroll
    for (int j = 0; j < 16; j++) Bv[j] = 0.f;
    if (lane == 0) Bv[0] = 1.f;               // alpha_{-1} = delta_0

    float pc[16], PaL[8], PaH[8];
    float Av0;
    float k1, k2, k4, k8, k16;

    // p-only prep from 4 row registers
    auto prep = [&](float4 f0, float4 f1, float4 f2, float4 f3) {
        pc[0]=f0.x;  pc[1]=f0.y;  pc[2]=f0.z;  pc[3]=f0.w;
        pc[4]=f1.x;  pc[5]=f1.y;  pc[6]=f1.z;  pc[7]=f1.w;
        pc[8]=f2.x;  pc[9]=f2.y;  pc[10]=f2.z; pc[11]=f2.w;
        pc[12]=f3.x; pc[13]=f3.y; pc[14]=f3.z; pc[15]=f3.w;
        float prevlast = __shfl_up_sync(0xffffffffu, pc[15], 1);
        Av0 = (lane == 0) ? 0.f : (1.f - prevlast);
        float Av[16];
        Av[0] = Av0;
#pragma unroll
        for (int j = 1; j < 16; j++) Av[j] = 1.f - pc[j-1];
        PaL[0] = Av[0];
#pragma unroll
        for (int j = 1; j < 8; j++) PaL[j] = PaL[j-1] * Av[j];
        PaH[0] = Av[8];
#pragma unroll
        for (int j = 1; j < 8; j++) PaH[j] = PaH[j-1] * Av[8+j];
        float m = PaL[7] * PaH[7], s;
        k1  = (lane >= 1)  ? m : 0.f;
        s = __shfl_up_sync(0xffffffffu, m, 1);  m *= s;
        k2  = (lane >= 2)  ? m : 0.f;
        s = __shfl_up_sync(0xffffffffu, m, 2);  m *= s;
        k4  = (lane >= 4)  ? m : 0.f;
        s = __shfl_up_sync(0xffffffffu, m, 4);  m *= s;
        k8  = (lane >= 8)  ? m : 0.f;
        s = __shfl_up_sync(0xffffffffu, m, 8);  m *= s;
        k16 = (lane >= 16) ? m : 0.f;
    };

    // initial prep from row 0 (resident)
    {
        const float4* base = srow + 0 * 128 + lane;
        prep(base[0], base[32], base[64], base[96]);
    }

    for (int i = 0; i < TGT; i++) {
        issue_row(i + 7);
        asm volatile("cp.async.wait_group 6;" ::: "memory");

        // hoisted LDS of row i+1 (resident since last iteration's wait)
        const float4* nbase = srow + (uint32_t)((i + 1) & 7) * 128 + lane;
        float4 nf0 = nbase[0];
        float4 nf1 = nbase[32];
        float4 nf2 = nbase[64];
        float4 nf3 = nbase[96];

        float Av[16];
        Av[0] = Av0;
#pragma unroll
        for (int j = 1; j < 16; j++) Av[j] = 1.f - pc[j-1];

        float Pl[8], Ph[8];
        Pl[0] = Bv[0];
#pragma unroll
        for (int j = 1; j < 8; j++) Pl[j] = fmaf(Pl[j-1], Av[j], Bv[j]);
        Ph[0] = Bv[8];
#pragma unroll
        for (int j = 1; j < 8; j++) Ph[j] = fmaf(Ph[j-1], Av[8+j], Bv[8+j]);

        float b = fmaf(Pl[7], PaH[7], Ph[7]);

        float s;
        s = __shfl_up_sync(0xffffffffu, b, 1);  b = fmaf(s, k1,  b);
        s = __shfl_up_sync(0xffffffffu, b, 2);  b = fmaf(s, k2,  b);
        s = __shfl_up_sync(0xffffffffu, b, 4);  b = fmaf(s, k4,  b);
        s = __shfl_up_sync(0xffffffffu, b, 8);  b = fmaf(s, k8,  b);
        s = __shfl_up_sync(0xffffffffu, b, 16); b = fmaf(s, k16, b);

        float qin = __shfl_up_sync(0xffffffffu, b, 1);
        qin = (lane == 0) ? 0.f : qin;
        float qmid = fmaf(qin, PaL[7], Pl[7]);

#pragma unroll
        for (int j = 0; j < 8; j++)
            Bv[j] = pc[j] * fmaf(qin, PaL[j], Pl[j]);
#pragma unroll
        for (int j = 0; j < 8; j++)
            Bv[8+j] = pc[8+j] * fmaf(qmid, PaH[j], Ph[j]);

        __stcs(ar + (size_t)i * 128 + 0, make_float4(Bv[0],  Bv[1],  Bv[2],  Bv[3]));
        __stcs(ar + (size_t)i * 128 + 1, make_float4(Bv[4],  Bv[5],  Bv[6],  Bv[7]));
        __stcs(ar + (size_t)i * 128 + 2, make_float4(Bv[8],  Bv[9],  Bv[10], Bv[11]));
        __stcs(ar + (size_t)i * 128 + 3, make_float4(Bv[12], Bv[13], Bv[14], Bv[15]));

        prep(nf0, nf1, nf2, nf3);
    }
}

// ---------------------------------------------------------------------------
extern "C" void kernel_launch(void* const* d_in, const int* in_sizes, int n_in,
                              void* d_out, int out_size)
{
    const float* seqs  = (const float*)d_in[0];
    const float* keys  = (const float*)d_in[1];
    const float* q_w   = (const float*)d_in[2];
    const float* q_b   = (const float*)d_in[3];
    const float* k_w   = (const float*)d_in[4];
    const float* k_b   = (const float*)d_in[5];
    const float* ebias = (const float*)d_in[6];

    float* p_out = (float*)d_out;
    float* a_out = p_out + P_ELEMS;

    void *sh, *sl, *kh, *kl, *qwh, *qwl, *kwh, *kwl;
    cudaGetSymbolAddress(&sh,  g_sh);  cudaGetSymbolAddress(&sl,  g_sl);
    cudaGetSymbolAddress(&kh,  g_kh);  cudaGetSymbolAddress(&kl,  g_kl);
    cudaGetSymbolAddress(&qwh, g_qwh); cudaGetSymbolAddress(&qwl, g_qwl);
    cudaGetSymbolAddress(&kwh, g_kwh); cudaGetSymbolAddress(&kwl, g_kwl);

    cudaFuncSetAttribute(proj_mma,   cudaFuncAttributeMaxDynamicSharedMemorySize, PROJ_SMEM);
    cudaFuncSetAttribute(energy_mma, cudaFuncAttributeMaxDynamicSharedMemorySize, E_SMEM);

    cvt_all<<<CVT_BLOCKS, 256>>>((const float4*)seqs, (const float4*)keys,
                                 (const float4*)q_w, (const float4*)k_w,
                                 (ushort4*)sh, (ushort4*)sl, (ushort4*)kh, (ushort4*)kl,
                                 (ushort4*)qwh, (ushort4*)qwl, (ushort4*)kwh, (ushort4*)kwl);

    proj_mma<<<dim3(8, 48), 256, PROJ_SMEM>>>(q_b, k_b);
    energy_mma<<<dim3(4, 2, BH), 256, E_SMEM>>>(ebias, p_out);
    alpha_kernel<<<BH, 32>>>(p_out, a_out);
}

// round 9
// speedup vs baseline: 2.8716x; 1.0290x over previous
#include <cuda_runtime.h>
#include <cuda_bf16.h>
#include <cstdint>

// ---------------------------------------------------------------------------
// B=8, TGT=256, SRC=512, D=1024, H=16, dh=64, TEMP=0.2
// Output: p_choose (8,16,256,512) then alpha (8,16,256,512), fp32.
// ---------------------------------------------------------------------------

#define D_DIM   1024
#define TGT     256
#define SRC     512
#define NB      8
#define NH      16
#define DH      64
#define BH      (NB*NH)
#define P_ELEMS ((size_t)BH*TGT*SRC)

#define MQ (NB*TGT)     // 2048
#define MK (NB*SRC)     // 4096

// bf16 hi/lo decompositions of inputs
__device__ __nv_bfloat16 g_sh[MQ*D_DIM], g_sl[MQ*D_DIM];
__device__ __nv_bfloat16 g_kh[MK*D_DIM], g_kl[MK*D_DIM];
__device__ __nv_bfloat16 g_qwh[D_DIM*D_DIM], g_qwl[D_DIM*D_DIM];
__device__ __nv_bfloat16 g_kwh[D_DIM*D_DIM], g_kwl[D_DIM*D_DIM];
// bf16 hi/lo activations (projection outputs)
__device__ __nv_bfloat16 g_aqh[MQ*D_DIM], g_aql[MQ*D_DIM];
__device__ __nv_bfloat16 g_akh[MK*D_DIM], g_akl[MK*D_DIM];

__device__ __forceinline__ void mma16816(float4& d,
    uint32_t a0, uint32_t a1, uint32_t a2, uint32_t a3,
    uint32_t b0, uint32_t b1)
{
    asm volatile(
        "mma.sync.aligned.m16n8k16.row.col.f32.bf16.bf16.f32 "
        "{%0,%1,%2,%3}, {%4,%5,%6,%7}, {%8,%9}, {%0,%1,%2,%3};"
        : "+f"(d.x), "+f"(d.y), "+f"(d.z), "+f"(d.w)
        : "r"(a0), "r"(a1), "r"(a2), "r"(a3), "r"(b0), "r"(b1));
}

__device__ __forceinline__ void ldm_x4(uint32_t& r0, uint32_t& r1,
                                       uint32_t& r2, uint32_t& r3, uint32_t addr)
{
    asm volatile("ldmatrix.sync.aligned.m8n8.x4.shared.b16 {%0,%1,%2,%3}, [%4];"
                 : "=r"(r0), "=r"(r1), "=r"(r2), "=r"(r3) : "r"(addr));
}

__device__ __forceinline__ void cp_async16(uint32_t smem_dst, const void* gsrc) {
    asm volatile("cp.async.ca.shared.global [%0], [%1], 16;" :: "r"(smem_dst), "l"(gsrc));
}
__device__ __forceinline__ void cp_async16_cg(uint32_t smem_dst, const void* gsrc) {
    asm volatile("cp.async.cg.shared.global [%0], [%1], 16;" :: "r"(smem_dst), "l"(gsrc));
}
__device__ __forceinline__ void cp_async_commit() {
    asm volatile("cp.async.commit_group;" ::: "memory");
}
__device__ __forceinline__ void cp_async_wait0() {
    asm volatile("cp.async.wait_group 0;" ::: "memory");
}
__device__ __forceinline__ uint32_t smem_u32(const void* p) {
    uint32_t a;
    asm("{ .reg .u64 t; cvta.to.shared.u64 t, %1; cvt.u32.u64 %0, t; }" : "=r"(a) : "l"(p));
    return a;
}

// ---------------------------------------------------------------------------
// Fused fp32 -> (hi, lo) bf16 decomposition for all 4 inputs (one launch).
// ---------------------------------------------------------------------------
#define N4_S  (MQ*D_DIM/4)           // 524288
#define N4_K  (MK*D_DIM/4)           // 1048576
#define N4_W  (D_DIM*D_DIM/4)        // 262144
#define CVT_BLOCKS ((N4_S + N4_K + 2*N4_W)/256)

__global__ __launch_bounds__(256)
void cvt_all(const float4* __restrict__ s,  const float4* __restrict__ k,
             const float4* __restrict__ qw, const float4* __restrict__ kw,
             ushort4* __restrict__ sh,  ushort4* __restrict__ sl,
             ushort4* __restrict__ kh,  ushort4* __restrict__ kl,
             ushort4* __restrict__ qwh, ushort4* __restrict__ qwl,
             ushort4* __restrict__ kwh, ushort4* __restrict__ kwl)
{
    int b = blockIdx.x;
    const float4* in; ushort4 *hi, *lo; int idx;
    if (b < N4_S/256) {
        in = s; hi = sh; lo = sl; idx = b * 256 + threadIdx.x;
    } else if (b < (N4_S + N4_K)/256) {
        in = k; hi = kh; lo = kl; idx = (b - N4_S/256) * 256 + threadIdx.x;
    } else if (b < (N4_S + N4_K + N4_W)/256) {
        in = qw; hi = qwh; lo = qwl; idx = (b - (N4_S + N4_K)/256) * 256 + threadIdx.x;
    } else {
        in = kw; hi = kwh; lo = kwl; idx = (b - (N4_S + N4_K + N4_W)/256) * 256 + threadIdx.x;
    }
    float4 v = in[idx];
    ushort4 h, l;
    {
        __nv_bfloat16 hb = __float2bfloat16(v.x);
        __nv_bfloat16 lb = __float2bfloat16(v.x - __bfloat162float(hb));
        h.x = *(unsigned short*)&hb; l.x = *(unsigned short*)&lb;
    }
    {
        __nv_bfloat16 hb = __float2bfloat16(v.y);
        __nv_bfloat16 lb = __float2bfloat16(v.y - __bfloat162float(hb));
        h.y = *(unsigned short*)&hb; l.y = *(unsigned short*)&lb;
    }
    {
        __nv_bfloat16 hb = __float2bfloat16(v.z);
        __nv_bfloat16 lb = __float2bfloat16(v.z - __bfloat162float(hb));
        h.z = *(unsigned short*)&hb; l.z = *(unsigned short*)&lb;
    }
    {
        __nv_bfloat16 hb = __float2bfloat16(v.w);
        __nv_bfloat16 lb = __float2bfloat16(v.w - __bfloat162float(hb));
        h.w = *(unsigned short*)&hb; l.w = *(unsigned short*)&lb;
    }
    hi[idx] = h; lo[idx] = l;
}

// ---------------------------------------------------------------------------
// mma.sync bf16-split projection GEMM + bias + ReLU -> bf16 hi/lo activations.
// CTA tile 128x128, 8 warps (4M x 2N). K chunk 32, cp.async x2, ldmatrix frags.
// launch_bounds(256, 2): force 2 CTAs/SM so chunk-boundary waits overlap.
// ---------------------------------------------------------------------------
#define CK      32
#define NCH     (D_DIM/CK)
#define STR     40
#define TILE_BYTES (128*STR*2)
#define BUF_BYTES  (4*TILE_BYTES)
#define PROJ_SMEM  (2*BUF_BYTES)     // 81920; x2 CTAs = 160KB <= 228KB

__global__ __launch_bounds__(256, 2)
void proj_mma(const float* __restrict__ q_b, const float* __restrict__ k_b)
{
    extern __shared__ char smem[];
    const int tid  = threadIdx.x;
    const int wid  = tid >> 5;
    const int lane = tid & 31;
    const int g    = lane >> 2;
    const int t    = lane & 3;
    const int warpM = wid & 3;
    const int warpN = wid >> 2;

    const int by  = blockIdx.y;
    const bool isq = by < 16;
    const int bm  = (isq ? by : by - 16) * 128;
    const int bn  = blockIdx.x * 128;

    const __nv_bfloat16* Ah = isq ? g_sh  : g_kh;
    const __nv_bfloat16* Al = isq ? g_sl  : g_kl;
    const __nv_bfloat16* Wh = isq ? g_qwh : g_kwh;
    const __nv_bfloat16* Wl = isq ? g_qwl : g_kwl;
    const float*       bias = isq ? q_b   : k_b;
    __nv_bfloat16*       CH = isq ? g_aqh : g_akh;
    __nv_bfloat16*       CL = isq ? g_aql : g_akl;

    float4 acc[2][8];
#pragma unroll
    for (int i = 0; i < 2; i++)
#pragma unroll
        for (int j = 0; j < 8; j++) acc[i][j] = make_float4(0.f, 0.f, 0.f, 0.f);

    const uint32_t smem_base = smem_u32(smem);

    const int aRow    = lane & 15;
    const int aColOff = (lane >> 4) * 8;
    const int wRowOff = (lane & 7) + ((lane >> 4) & 1) * 8;
    const int wColOff = ((lane >> 3) & 1) * 8;

    auto load_chunk = [&](int c, int buf) {
        const int k0 = c * CK;
        const uint32_t sb = smem_base + buf * BUF_BYTES;
#pragma unroll
        for (int h = 0; h < 2; h++) {
            int seg = tid + h * 256;
            int row = seg >> 2;
            int s4  = seg & 3;
            uint32_t soff = (uint32_t)(row * STR + s4 * 8) * 2;
            size_t ga = (size_t)(bm + row) * D_DIM + k0 + s4 * 8;
            size_t gw = (size_t)(bn + row) * D_DIM + k0 + s4 * 8;
            cp_async16(sb + soff,                Ah + ga);
            cp_async16(sb + TILE_BYTES   + soff, Al + ga);
            cp_async16(sb + 2*TILE_BYTES + soff, Wh + gw);
            cp_async16(sb + 3*TILE_BYTES + soff, Wl + gw);
        }
        cp_async_commit();
    };

    load_chunk(0, 0);
    cp_async_wait0();
    __syncthreads();

    for (int c = 0; c < NCH; c++) {
        const int buf = c & 1;
        if (c + 1 < NCH) load_chunk(c + 1, buf ^ 1);

        const uint32_t sbAh = smem_base + buf * BUF_BYTES;
        const uint32_t sbAl = sbAh + TILE_BYTES;
        const uint32_t sbWh = sbAh + 2*TILE_BYTES;
        const uint32_t sbWl = sbAh + 3*TILE_BYTES;

        uint32_t aH0 = sbAh + (uint32_t)((warpM*32 +      aRow) * STR + aColOff) * 2;
        uint32_t aH1 = sbAh + (uint32_t)((warpM*32 + 16 + aRow) * STR + aColOff) * 2;
        uint32_t aL0 = sbAl + (uint32_t)((warpM*32 +      aRow) * STR + aColOff) * 2;
        uint32_t aL1 = sbAl + (uint32_t)((warpM*32 + 16 + aRow) * STR + aColOff) * 2;
        uint32_t wH  = sbWh + (uint32_t)((warpN*64 + wRowOff) * STR + wColOff) * 2;
        uint32_t wL  = sbWl + (uint32_t)((warpN*64 + wRowOff) * STR + wColOff) * 2;

#pragma unroll
        for (int ks = 0; ks < CK; ks += 16) {
            const uint32_t kso = (uint32_t)ks * 2;
            uint32_t ah[2][4], al[2][4];
            ldm_x4(ah[0][0], ah[0][1], ah[0][2], ah[0][3], aH0 + kso);
            ldm_x4(ah[1][0], ah[1][1], ah[1][2], ah[1][3], aH1 + kso);
            ldm_x4(al[0][0], al[0][1], al[0][2], al[0][3], aL0 + kso);
            ldm_x4(al[1][0], al[1][1], al[1][2], al[1][3], aL1 + kso);
#pragma unroll
            for (int jj = 0; jj < 8; jj += 2) {
                const uint32_t joff = (uint32_t)(jj * 8 * STR) * 2;
                uint32_t bh0a, bh1a, bh0b, bh1b;
                ldm_x4(bh0a, bh1a, bh0b, bh1b, wH + joff + kso);
                uint32_t bl0a, bl1a, bl0b, bl1b;
                ldm_x4(bl0a, bl1a, bl0b, bl1b, wL + joff + kso);
#pragma unroll
                for (int i = 0; i < 2; i++) {
                    mma16816(acc[i][jj],   ah[i][0], ah[i][1], ah[i][2], ah[i][3], bh0a, bh1a);
                    mma16816(acc[i][jj],   ah[i][0], ah[i][1], ah[i][2], ah[i][3], bl0a, bl1a);
                    mma16816(acc[i][jj],   al[i][0], al[i][1], al[i][2], al[i][3], bh0a, bh1a);
                    mma16816(acc[i][jj+1], ah[i][0], ah[i][1], ah[i][2], ah[i][3], bh0b, bh1b);
                    mma16816(acc[i][jj+1], ah[i][0], ah[i][1], ah[i][2], ah[i][3], bl0b, bl1b);
                    mma16816(acc[i][jj+1], al[i][0], al[i][1], al[i][2], al[i][3], bh0b, bh1b);
                }
            }
        }

        cp_async_wait0();
        __syncthreads();
    }

#pragma unroll
    for (int i = 0; i < 2; i++) {
        int row0 = bm + warpM * 32 + i * 16 + g;
#pragma unroll
        for (int j = 0; j < 8; j++) {
            int col = bn + warpN * 64 + j * 8 + 2 * t;
            float b0 = bias[col], b1 = bias[col + 1];
            float v[4];
            v[0] = fmaxf(acc[i][j].x + b0, 0.f);
            v[1] = fmaxf(acc[i][j].y + b1, 0.f);
            v[2] = fmaxf(acc[i][j].z + b0, 0.f);
            v[3] = fmaxf(acc[i][j].w + b1, 0.f);
            __nv_bfloat16 h[4], l[4];
#pragma unroll
            for (int u = 0; u < 4; u++) {
                h[u] = __float2bfloat16(v[u]);
                l[u] = __float2bfloat16(v[u] - __bfloat162float(h[u]));
            }
            __nv_bfloat162 h01; h01.x = h[0]; h01.y = h[1];
            __nv_bfloat162 h23; h23.x = h[2]; h23.y = h[3];
            __nv_bfloat162 l01; l01.x = l[0]; l01.y = l[1];
            __nv_bfloat162 l23; l23.x = l[2]; l23.y = l[3];
            *(__nv_bfloat162*)(CH + (size_t)row0 * D_DIM + col)       = h01;
            *(__nv_bfloat162*)(CH + (size_t)(row0 + 8) * D_DIM + col) = h23;
            *(__nv_bfloat162*)(CL + (size_t)row0 * D_DIM + col)       = l01;
            *(__nv_bfloat162*)(CL + (size_t)(row0 + 8) * D_DIM + col) = l23;
        }
    }
}

// ---------------------------------------------------------------------------
// mma.sync bf16-split energy + sigmoid (unchanged — known-passing).
// ---------------------------------------------------------------------------
#define ESTR    72
#define ETILE_BYTES (128*ESTR*2)
#define E_SMEM  (4*ETILE_BYTES)

__global__ __launch_bounds__(256)
void energy_mma(const float* __restrict__ ebias, float* __restrict__ P)
{
    extern __shared__ char smem[];
    const int tid  = threadIdx.x;
    const int wid  = tid >> 5;
    const int lane = tid & 31;
    const int g    = lane >> 2;
    const int t    = lane & 3;
    const int warpM = wid & 3;
    const int warpN = wid >> 2;

    const int bh = blockIdx.z;
    const int bb = bh >> 4;
    const int hh = bh & 15;
    const int m0 = blockIdx.y * 128;
    const int n0 = blockIdx.x * 128;

    const __nv_bfloat16* Qh = g_aqh + (size_t)bb * TGT * D_DIM + hh * DH;
    const __nv_bfloat16* Ql = g_aql + (size_t)bb * TGT * D_DIM + hh * DH;
    const __nv_bfloat16* Kh = g_akh + (size_t)bb * SRC * D_DIM + hh * DH;
    const __nv_bfloat16* Kl = g_akl + (size_t)bb * SRC * D_DIM + hh * DH;

    const uint32_t sb = smem_u32(smem);

#pragma unroll
    for (int h = 0; h < 4; h++) {
        int seg = tid + h * 256;
        int row = seg >> 3;
        int s   = seg & 7;
        uint32_t soff = (uint32_t)(row * ESTR + s * 8) * 2;
        cp_async16(sb + soff,                 Qh + (size_t)(m0 + row) * D_DIM + s * 8);
        cp_async16(sb + ETILE_BYTES   + soff, Ql + (size_t)(m0 + row) * D_DIM + s * 8);
        cp_async16(sb + 2*ETILE_BYTES + soff, Kh + (size_t)(n0 + row) * D_DIM + s * 8);
        cp_async16(sb + 3*ETILE_BYTES + soff, Kl + (size_t)(n0 + row) * D_DIM + s * 8);
    }
    cp_async_commit();
    cp_async_wait0();
    __syncthreads();

    const __nv_bfloat16* sQh = (const __nv_bfloat16*)smem;
    const __nv_bfloat16* sQl = (const __nv_bfloat16*)(smem + ETILE_BYTES);
    const __nv_bfloat16* sKh = (const __nv_bfloat16*)(smem + 2*ETILE_BYTES);
    const __nv_bfloat16* sKl = (const __nv_bfloat16*)(smem + 3*ETILE_BYTES);

    float4 acc[2][8];
#pragma unroll
    for (int i = 0; i < 2; i++)
#pragma unroll
        for (int j = 0; j < 8; j++) acc[i][j] = make_float4(0.f, 0.f, 0.f, 0.f);

#pragma unroll
    for (int ks = 0; ks < DH; ks += 16) {
        uint32_t ah[2][4], al[2][4];
#pragma unroll
        for (int i = 0; i < 2; i++) {
            int r0 = warpM * 32 + i * 16 + g;
            const __nv_bfloat16* p0 = sQh + r0 * ESTR + ks + 2 * t;
            const __nv_bfloat16* p1 = sQh + (r0 + 8) * ESTR + ks + 2 * t;
            ah[i][0] = *(const uint32_t*)p0;
            ah[i][1] = *(const uint32_t*)p1;
            ah[i][2] = *(const uint32_t*)(p0 + 8);
            ah[i][3] = *(const uint32_t*)(p1 + 8);
            const __nv_bfloat16* q0 = sQl + r0 * ESTR + ks + 2 * t;
            const __nv_bfloat16* q1 = sQl + (r0 + 8) * ESTR + ks + 2 * t;
            al[i][0] = *(const uint32_t*)q0;
            al[i][1] = *(const uint32_t*)q1;
            al[i][2] = *(const uint32_t*)(q0 + 8);
            al[i][3] = *(const uint32_t*)(q1 + 8);
        }
#pragma unroll
        for (int j = 0; j < 8; j++) {
            int rw = warpN * 64 + j * 8 + g;
            const __nv_bfloat16* pw = sKh + rw * ESTR + ks + 2 * t;
            uint32_t bh0 = *(const uint32_t*)pw;
            uint32_t bh1 = *(const uint32_t*)(pw + 8);
            const __nv_bfloat16* pl = sKl + rw * ESTR + ks + 2 * t;
            uint32_t bl0 = *(const uint32_t*)pl;
            uint32_t bl1 = *(const uint32_t*)(pl + 8);
#pragma unroll
            for (int i = 0; i < 2; i++) {
                mma16816(acc[i][j], ah[i][0], ah[i][1], ah[i][2], ah[i][3], bh0, bh1);
                mma16816(acc[i][j], ah[i][0], ah[i][1], ah[i][2], ah[i][3], bl0, bl1);
                mma16816(acc[i][j], al[i][0], al[i][1], al[i][2], al[i][3], bh0, bh1);
            }
        }
    }

    const float eb5 = ebias[0] * 5.0f;

#pragma unroll
    for (int i = 0; i < 2; i++) {
        int row0 = m0 + warpM * 32 + i * 16 + g;
#pragma unroll
        for (int j = 0; j < 8; j++) {
            int col = n0 + warpN * 64 + j * 8 + 2 * t;
            float z0 = fmaf(acc[i][j].x, 0.625f, eb5);
            float z1 = fmaf(acc[i][j].y, 0.625f, eb5);
            float z2 = fmaf(acc[i][j].z, 0.625f, eb5);
            float z3 = fmaf(acc[i][j].w, 0.625f, eb5);
            float2 o0, o1;
            o0.x = 1.0f / (1.0f + __expf(-z0));
            o0.y = 1.0f / (1.0f + __expf(-z1));
            o1.x = 1.0f / (1.0f + __expf(-z2));
            o1.y = 1.0f / (1.0f + __expf(-z3));
            float* dst0 = P + ((size_t)bh * TGT + row0) * SRC + col;
            float* dst1 = P + ((size_t)bh * TGT + row0 + 8) * SRC + col;
            *(float2*)dst0 = o0;
            *(float2*)dst1 = o1;
        }
    }
}

// ---------------------------------------------------------------------------
// Monotonic alignment v6: v5 with persistent Av (no per-step recompute).
// ---------------------------------------------------------------------------
__global__ __launch_bounds__(32)
void alpha_kernel(const float* __restrict__ p, float* __restrict__ alpha)
{
    __shared__ float4 srow[8 * 128];          // 8 slots x 2048B ring
    const int lane = threadIdx.x;
    const int bh   = blockIdx.x;

    const float* pg = p + (size_t)bh * TGT * SRC;
    float4*      ar = (float4*)(alpha + (size_t)bh * TGT * SRC + lane * 16);
    const uint32_t sbase = smem_u32(srow);

    auto issue_row = [&](int r) {
        int rc = (r < TGT) ? r : (TGT - 1);
        uint32_t slot = (uint32_t)(r & 7);
        const float* src = pg + (size_t)rc * SRC + lane * 16;
#pragma unroll
        for (int c = 0; c < 4; c++)
            cp_async16_cg(sbase + slot * 2048 + (uint32_t)(c * 32 + lane) * 16,
                          src + c * 4);
        cp_async_commit();
    };

#pragma unroll
    for (int r = 0; r < 7; r++) issue_row(r);
    asm volatile("cp.async.wait_group 6;" ::: "memory");

    float Bv[16];
#pragma unroll
    for (int j = 0; j < 16; j++) Bv[j] = 0.f;
    if (lane == 0) Bv[0] = 1.f;               // alpha_{-1} = delta_0

    float pc[16], Av[16], PaL[8], PaH[8];
    float k1, k2, k4, k8, k16;

    // p-only prep from 4 row registers; Av persists for the compute step
    auto prep = [&](float4 f0, float4 f1, float4 f2, float4 f3) {
        pc[0]=f0.x;  pc[1]=f0.y;  pc[2]=f0.z;  pc[3]=f0.w;
        pc[4]=f1.x;  pc[5]=f1.y;  pc[6]=f1.z;  pc[7]=f1.w;
        pc[8]=f2.x;  pc[9]=f2.y;  pc[10]=f2.z; pc[11]=f2.w;
        pc[12]=f3.x; pc[13]=f3.y; pc[14]=f3.z; pc[15]=f3.w;
        float prevlast = __shfl_up_sync(0xffffffffu, pc[15], 1);
        Av[0] = (lane == 0) ? 0.f : (1.f - prevlast);
#pragma unroll
        for (int j = 1; j < 16; j++) Av[j] = 1.f - pc[j-1];
        PaL[0] = Av[0];
#pragma unroll
        for (int j = 1; j < 8; j++) PaL[j] = PaL[j-1] * Av[j];
        PaH[0] = Av[8];
#pragma unroll
        for (int j = 1; j < 8; j++) PaH[j] = PaH[j-1] * Av[8+j];
        float m = PaL[7] * PaH[7], s;
        k1  = (lane >= 1)  ? m : 0.f;
        s = __shfl_up_sync(0xffffffffu, m, 1);  m *= s;
        k2  = (lane >= 2)  ? m : 0.f;
        s = __shfl_up_sync(0xffffffffu, m, 2);  m *= s;
        k4  = (lane >= 4)  ? m : 0.f;
        s = __shfl_up_sync(0xffffffffu, m, 4);  m *= s;
        k8  = (lane >= 8)  ? m : 0.f;
        s = __shfl_up_sync(0xffffffffu, m, 8);  m *= s;
        k16 = (lane >= 16) ? m : 0.f;
    };

    {
        const float4* base = srow + 0 * 128 + lane;
        prep(base[0], base[32], base[64], base[96]);
    }

    for (int i = 0; i < TGT; i++) {
        issue_row(i + 7);
        asm volatile("cp.async.wait_group 6;" ::: "memory");

        // hoisted LDS of row i+1 (resident since the previous wait)
        const float4* nbase = srow + (uint32_t)((i + 1) & 7) * 128 + lane;
        float4 nf0 = nbase[0];
        float4 nf1 = nbase[32];
        float4 nf2 = nbase[64];
        float4 nf3 = nbase[96];

        // two independent 8-long half-chains (Av persistent from prep)
        float Pl[8], Ph[8];
        Pl[0] = Bv[0];
#pragma unroll
        for (int j = 1; j < 8; j++) Pl[j] = fmaf(Pl[j-1], Av[j], Bv[j]);
        Ph[0] = Bv[8];
#pragma unroll
        for (int j = 1; j < 8; j++) Ph[j] = fmaf(Ph[j-1], Av[8+j], Bv[8+j]);

        float b = fmaf(Pl[7], PaH[7], Ph[7]);

        float s;
        s = __shfl_up_sync(0xffffffffu, b, 1);  b = fmaf(s, k1,  b);
        s = __shfl_up_sync(0xffffffffu, b, 2);  b = fmaf(s, k2,  b);
        s = __shfl_up_sync(0xffffffffu, b, 4);  b = fmaf(s, k4,  b);
        s = __shfl_up_sync(0xffffffffu, b, 8);  b = fmaf(s, k8,  b);
        s = __shfl_up_sync(0xffffffffu, b, 16); b = fmaf(s, k16, b);

        float qin = __shfl_up_sync(0xffffffffu, b, 1);
        qin = (lane == 0) ? 0.f : qin;
        float qmid = fmaf(qin, PaL[7], Pl[7]);

#pragma unroll
        for (int j = 0; j < 8; j++)
            Bv[j] = pc[j] * fmaf(qin, PaL[j], Pl[j]);
#pragma unroll
        for (int j = 0; j < 8; j++)
            Bv[8+j] = pc[8+j] * fmaf(qmid, PaH[j], Ph[j]);

        __stcs(ar + (size_t)i * 128 + 0, make_float4(Bv[0],  Bv[1],  Bv[2],  Bv[3]));
        __stcs(ar + (size_t)i * 128 + 1, make_float4(Bv[4],  Bv[5],  Bv[6],  Bv[7]));
        __stcs(ar + (size_t)i * 128 + 2, make_float4(Bv[8],  Bv[9],  Bv[10], Bv[11]));
        __stcs(ar + (size_t)i * 128 + 3, make_float4(Bv[12], Bv[13], Bv[14], Bv[15]));

        prep(nf0, nf1, nf2, nf3);
    }
}

// ---------------------------------------------------------------------------
extern "C" void kernel_launch(void* const* d_in, const int* in_sizes, int n_in,
                              void* d_out, int out_size)
{
    const float* seqs  = (const float*)d_in[0];
    const float* keys  = (const float*)d_in[1];
    const float* q_w   = (const float*)d_in[2];
    const float* q_b   = (const float*)d_in[3];
    const float* k_w   = (const float*)d_in[4];
    const float* k_b   = (const float*)d_in[5];
    const float* ebias = (const float*)d_in[6];

    float* p_out = (float*)d_out;
    float* a_out = p_out + P_ELEMS;

    void *sh, *sl, *kh, *kl, *qwh, *qwl, *kwh, *kwl;
    cudaGetSymbolAddress(&sh,  g_sh);  cudaGetSymbolAddress(&sl,  g_sl);
    cudaGetSymbolAddress(&kh,  g_kh);  cudaGetSymbolAddress(&kl,  g_kl);
    cudaGetSymbolAddress(&qwh, g_qwh); cudaGetSymbolAddress(&qwl, g_qwl);
    cudaGetSymbolAddress(&kwh, g_kwh); cudaGetSymbolAddress(&kwl, g_kwl);

    cudaFuncSetAttribute(proj_mma,   cudaFuncAttributeMaxDynamicSharedMemorySize, PROJ_SMEM);
    cudaFuncSetAttribute(energy_mma, cudaFuncAttributeMaxDynamicSharedMemorySize, E_SMEM);

    cvt_all<<<CVT_BLOCKS, 256>>>((const float4*)seqs, (const float4*)keys,
                                 (const float4*)q_w, (const float4*)k_w,
                                 (ushort4*)sh, (ushort4*)sl, (ushort4*)kh, (ushort4*)kl,
                                 (ushort4*)qwh, (ushort4*)qwl, (ushort4*)kwh, (ushort4*)kwl);

    proj_mma<<<dim3(8, 48), 256, PROJ_SMEM>>>(q_b, k_b);
    energy_mma<<<dim3(4, 2, BH), 256, E_SMEM>>>(ebias, p_out);
    alpha_kernel<<<BH, 32>>>(p_out, a_out);
}